// round 8
// baseline (speedup 1.0000x reference)
#include <cuda_runtime.h>
#include <cuda_bf16.h>
#include <math.h>
#include <stdint.h>

#define EPSV 1e-6f
using bf16 = __nv_bfloat16;

constexpr int B = 2, S = 1024, D = 1024, H = 16, HD = 64;
constexpr int BS = B * S;                         // 2048
constexpr size_t PROJ = (size_t)BS * D;           // 2M
constexpr size_t ATTN = (size_t)B * H * S * S;    // 32M
constexpr size_t WSZ  = (size_t)D * D;            // 1M
#define C0V (1e-4f + EPSV)                        // top_var + eps (constant part of attn_var)

// ---------------- scratch (device globals; no dynamic allocation) ----------
__device__ float g_colsum[B * D];
__device__ bf16 g_amuh[ATTN], g_amul[ATTN], g_avarw[ATTN];
__device__ bf16 g_qh[PROJ], g_ql[PROJ], g_kh[PROJ], g_kl[PROJ];
__device__ bf16 g_vh[PROJ], g_vl[PROJ], g_vsh[PROJ];
__device__ bf16 g_qmh[PROJ], g_qml[PROJ], g_kmh[PROJ], g_kml[PROJ];
__device__ bf16 g_vmh[PROJ], g_vml[PROJ], g_vvh[PROJ];
__device__ bf16 g_ymh[PROJ], g_yml[PROJ], g_pph[PROJ];
__device__ bf16 g_wqh[WSZ], g_wql[WSZ], g_wkh[WSZ], g_wkl[WSZ];
__device__ bf16 g_wvh[WSZ], g_wvl[WSZ], g_wvsh[WSZ];
__device__ bf16 g_woh[WSZ], g_wol[WSZ], g_wosh[WSZ];

// ---------------- helpers --------------------------------------------------
__device__ __forceinline__ uint32_t smem_u32(const void* p) {
    uint32_t a;
    asm("{ .reg .u64 t; cvta.to.shared.u64 t, %1; cvt.u32.u64 %0, t; }" : "=r"(a) : "l"(p));
    return a;
}
#define SWZ(o) ((o) ^ (((o) >> 3) & 0x70))

__device__ __forceinline__ void cp16(uint32_t dst, const void* src) {
    asm volatile("cp.async.cg.shared.global [%0], [%1], 16;" :: "r"(dst), "l"(src));
}
__device__ __forceinline__ void cp_commit() {
    asm volatile("cp.async.commit_group;" ::: "memory");
}
template<int N>
__device__ __forceinline__ void cp_wait() {
    asm volatile("cp.async.wait_group %0;" :: "n"(N) : "memory");
}
__device__ __forceinline__ void ldsm4(uint32_t& r0, uint32_t& r1, uint32_t& r2, uint32_t& r3,
                                      uint32_t addr) {
    asm volatile("ldmatrix.sync.aligned.m8n8.x4.shared.b16 {%0,%1,%2,%3}, [%4];"
                 : "=r"(r0), "=r"(r1), "=r"(r2), "=r"(r3) : "r"(addr));
}
__device__ __forceinline__ void ldsm4t(uint32_t& r0, uint32_t& r1, uint32_t& r2, uint32_t& r3,
                                       uint32_t addr) {
    asm volatile("ldmatrix.sync.aligned.m8n8.x4.trans.shared.b16 {%0,%1,%2,%3}, [%4];"
                 : "=r"(r0), "=r"(r1), "=r"(r2), "=r"(r3) : "r"(addr));
}
__device__ __forceinline__ void mma16816(float* d, const uint32_t* a, const uint32_t* b) {
    asm volatile(
        "mma.sync.aligned.m16n8k16.row.col.f32.bf16.bf16.f32 "
        "{%0,%1,%2,%3}, {%4,%5,%6,%7}, {%8,%9}, {%0,%1,%2,%3};"
        : "+f"(d[0]), "+f"(d[1]), "+f"(d[2]), "+f"(d[3])
        : "r"(a[0]), "r"(a[1]), "r"(a[2]), "r"(a[3]), "r"(b[0]), "r"(b[1]));
}
__device__ __forceinline__ void split2(float v, bf16& h, bf16& l) {
    h = __float2bfloat16(v);
    l = __float2bfloat16(v - __bfloat162float(h));
}
__device__ __forceinline__ void store_hl2(bf16* Ph, bf16* Pl, size_t idx, float v0, float v1) {
    bf16 h0, l0, h1, l1;
    split2(v0, h0, l0); split2(v1, h1, l1);
    __nv_bfloat162 ph; ph.x = h0; ph.y = h1;
    __nv_bfloat162 pl; pl.x = l0; pl.y = l1;
    *(__nv_bfloat162*)(Ph + idx) = ph;
    *(__nv_bfloat162*)(Pl + idx) = pl;
}
__device__ __forceinline__ void store_h2(bf16* Ph, size_t idx, float v0, float v1) {
    __nv_bfloat162 ph;
    ph.x = __float2bfloat16(v0); ph.y = __float2bfloat16(v1);
    *(__nv_bfloat162*)(Ph + idx) = ph;
}

// ---------------------------------------------------------------------------
// convert_all: fp32 -> (bf16 hi [, bf16 lo]), optional square; also zeros colsum
// ---------------------------------------------------------------------------
struct CvtParams {
    const float* src[10];
    bf16* hi[10];
    bf16* lo[10];      // nullptr -> hi only
    int n[10];
    int sq[10];
    float* cs;
};

__global__ void __launch_bounds__(256) convert_all(CvtParams P) {
    if (blockIdx.y == 0 && blockIdx.x == 0) {
        for (int i = threadIdx.x; i < B * D; i += 256) P.cs[i] = 0.f;
    }
    const int r = blockIdx.y;
    const int i4 = (blockIdx.x * 256 + threadIdx.x) * 4;
    if (i4 >= P.n[r]) return;
    float4 v = *(const float4*)(P.src[r] + i4);
    if (P.sq[r]) { v.x *= v.x; v.y *= v.y; v.z *= v.z; v.w *= v.w; }
    if (P.lo[r]) {
        store_hl2(P.hi[r], P.lo[r], i4, v.x, v.y);
        store_hl2(P.hi[r], P.lo[r], i4 + 2, v.z, v.w);
    } else {
        store_h2(P.hi[r], i4, v.x, v.y);
        store_h2(P.hi[r], i4 + 2, v.z, v.w);
    }
}

// ---------------------------------------------------------------------------
// colsum_kernel: cs[b*D+d] = sum_t vv[b,t,d]
// ---------------------------------------------------------------------------
__global__ void __launch_bounds__(256) colsum_kernel(float* cs, const bf16* vv) {
    const int d = blockIdx.x * 256 + threadIdx.x;
    const int b = d >> 10, dd = d & 1023;
    const int t0 = blockIdx.y * 64;
    const bf16* p = vv + (size_t)b * S * D + (size_t)t0 * D + dd;
    float s = 0.f;
    #pragma unroll 8
    for (int t = 0; t < 64; t++) s += __bfloat162float(p[(size_t)t * D]);
    atomicAdd(cs + d, s);
}

// ---------------------------------------------------------------------------
// Batched GEMM (unchanged from R7)
// ---------------------------------------------------------------------------
constexpr int GK = 1024;
constexpr int GN = 1024;
constexpr uint32_t TILE_B  = 16384;
constexpr uint32_t STAGE_B = 4 * TILE_B;
constexpr uint32_t GSMEM   = 3 * STAGE_B + 1024;

struct GemmArgs {
    const bf16 *Ah, *Al, *Bh, *Bl;
    const float* bias;
    float* Cf;
    bf16 *Ch, *Cl;
    int epi;
    int passes;
};
struct GemmBatch { GemmArgs a[4]; };

__global__ void __launch_bounds__(256, 1) gemm_mma_b(GemmBatch bat)
{
    extern __shared__ char dsraw[];
    char* dsm = (char*)(((uintptr_t)dsraw + 1023) & ~(uintptr_t)1023);
    const uint32_t base = smem_u32(dsm);

    const GemmArgs ga = bat.a[blockIdx.z];
    const bool p3 = (ga.passes == 3);

    const int tid  = threadIdx.x;
    const int wid  = tid >> 5;
    const int lane = tid & 31;
    const int wm = wid & 3;
    const int wn = wid >> 2;
    const int row0 = blockIdx.y * 128;
    const int col0 = blockIdx.x * 128;

    const int lr = tid >> 1;
    const int ls0 = (tid & 1) * 4;
    const size_t aoff = (size_t)(row0 + lr) * GK;
    const size_t boff = (size_t)(col0 + lr) * GK;

    auto load_chunk = [&](int c, int st) {
        const uint32_t sb = base + st * STAGE_B;
        const int k0 = c * 64;
        #pragma unroll
        for (int i = 0; i < 4; i++) {
            const int sg = ls0 + i;
            const uint32_t so = SWZ((uint32_t)(lr * 128 + sg * 16));
            const size_t gai = aoff + k0 + sg * 8;
            const size_t gbi = boff + k0 + sg * 8;
            cp16(sb + so,              ga.Ah + gai);
            cp16(sb + 2 * TILE_B + so, ga.Bh + gbi);
            if (p3) {
                cp16(sb + TILE_B + so,     ga.Al + gai);
                cp16(sb + 3 * TILE_B + so, ga.Bl + gbi);
            }
        }
    };

    float acc[2][8][4];
    #pragma unroll
    for (int mi = 0; mi < 2; mi++)
        #pragma unroll
        for (int ni = 0; ni < 8; ni++)
            #pragma unroll
            for (int q = 0; q < 4; q++) acc[mi][ni][q] = 0.f;

    const int a_r = wm * 32 + (lane & 15);
    const int a_kseg = (lane >> 4);
    const int b_r = wn * 64 + ((lane >> 4) & 1) * 8 + (lane & 7);
    const int b_kseg = (lane >> 3) & 1;

    load_chunk(0, 0); cp_commit();
    load_chunk(1, 1); cp_commit();

    for (int c = 0; c < 16; c++) {
        if (c + 2 < 16) load_chunk(c + 2, (c + 2) % 3);
        cp_commit();
        cp_wait<2>();
        __syncthreads();

        const uint32_t sA = base + (c % 3) * STAGE_B;
        const uint32_t sB = sA + 2 * TILE_B;

        #pragma unroll
        for (int ks = 0; ks < 4; ks++) {
            const int k0 = ks * 16;
            uint32_t bh_[16], bl_[16];
            #pragma unroll
            for (int p = 0; p < 4; p++) {
                const uint32_t bo = SWZ((uint32_t)((b_r + p * 16) * 128 +
                                                   (k0 + b_kseg * 8) * 2));
                ldsm4(bh_[4 * p], bh_[4 * p + 1], bh_[4 * p + 2], bh_[4 * p + 3], sB + bo);
                if (p3)
                    ldsm4(bl_[4 * p], bl_[4 * p + 1], bl_[4 * p + 2], bl_[4 * p + 3],
                          sB + TILE_B + bo);
            }
            #pragma unroll
            for (int mi = 0; mi < 2; mi++) {
                const uint32_t ao = SWZ((uint32_t)((a_r + mi * 16) * 128 +
                                                   (k0 + a_kseg * 8) * 2));
                uint32_t ah[4], al[4];
                ldsm4(ah[0], ah[1], ah[2], ah[3], sA + ao);
                if (p3) ldsm4(al[0], al[1], al[2], al[3], sA + TILE_B + ao);
                #pragma unroll
                for (int ni = 0; ni < 8; ni++) {
                    mma16816(acc[mi][ni], ah, &bh_[ni * 2]);
                    if (p3) {
                        mma16816(acc[mi][ni], ah, &bl_[ni * 2]);
                        mma16816(acc[mi][ni], al, &bh_[ni * 2]);
                    }
                }
            }
        }
        __syncthreads();
    }

    const int er = lane >> 2;
    const int ec = (lane & 3) * 2;
    const int epi = ga.epi;

    if (epi <= 2) {
        #pragma unroll
        for (int mi = 0; mi < 2; mi++) {
            #pragma unroll
            for (int ni = 0; ni < 8; ni++) {
                const int gr = row0 + wm * 32 + mi * 16 + er;
                const int gc = col0 + wn * 64 + ni * 8 + ec;
                float v0 = acc[mi][ni][0], v1 = acc[mi][ni][1];
                float v2 = acc[mi][ni][2], v3 = acc[mi][ni][3];
                if (epi == 0) {
                    const float b0 = ga.bias[gc], b1 = ga.bias[gc + 1];
                    v0 += b0; v1 += b1; v2 += b0; v3 += b1;
                } else {
                    v0 = sqrtf(v0); v1 = sqrtf(v1); v2 = sqrtf(v2); v3 = sqrtf(v3);
                }
                float2 w0 = {v0, v1}, w1 = {v2, v3};
                *(float2*)(ga.Cf + (size_t)gr * GN + gc)       = w0;
                *(float2*)(ga.Cf + (size_t)(gr + 8) * GN + gc) = w1;
            }
        }
    } else if (epi == 3) {
        bf16* Hs = (bf16*)dsm;
        bf16* Ls = (bf16*)(dsm + 32768);
        #pragma unroll
        for (int mi = 0; mi < 2; mi++) {
            #pragma unroll
            for (int ni = 0; ni < 8; ni++) {
                const int rl = wm * 32 + mi * 16 + er;
                const int cl = wn * 64 + ni * 8 + ec;
                float v0 = acc[mi][ni][0], v1 = acc[mi][ni][1];
                float v2 = acc[mi][ni][2], v3 = acc[mi][ni][3];
                const float b0 = ga.bias[col0 + cl], b1 = ga.bias[col0 + cl + 1];
                v0 += b0; v1 += b1; v2 += b0; v3 += b1;
                bf16 h0, l0, h1, l1;
                split2(v0, h0, l0); split2(v1, h1, l1);
                __nv_bfloat162 ph; ph.x = h0; ph.y = h1;
                __nv_bfloat162 pl; pl.x = l0; pl.y = l1;
                *(__nv_bfloat162*)(Hs + rl * 128 + cl) = ph;
                *(__nv_bfloat162*)(Ls + rl * 128 + cl) = pl;
                split2(v2, h0, l0); split2(v3, h1, l1);
                ph.x = h0; ph.y = h1; pl.x = l0; pl.y = l1;
                *(__nv_bfloat162*)(Hs + (rl + 8) * 128 + cl) = ph;
                *(__nv_bfloat162*)(Ls + (rl + 8) * 128 + cl) = pl;
            }
        }
        __syncthreads();
        #pragma unroll
        for (int i = 0; i < 8; i++) {
            const int idx = i * 256 + tid;
            const int r = idx >> 4;
            const int sg = idx & 15;
            const size_t gp = (size_t)(row0 + r) * GN + col0 + sg * 8;
            *(uint4*)(ga.Ch + gp) = *(const uint4*)((const char*)Hs + r * 256 + sg * 16);
            *(uint4*)(ga.Cl + gp) = *(const uint4*)((const char*)Ls + r * 256 + sg * 16);
        }
    } else {   // epi == 5
        bf16* Hs = (bf16*)dsm;
        #pragma unroll
        for (int mi = 0; mi < 2; mi++) {
            #pragma unroll
            for (int ni = 0; ni < 8; ni++) {
                const int rl = wm * 32 + mi * 16 + er;
                const int cl = wn * 64 + ni * 8 + ec;
                float v0 = acc[mi][ni][0], v1 = acc[mi][ni][1];
                float v2 = acc[mi][ni][2], v3 = acc[mi][ni][3];
                float s;
                s = sqrtf(v0) + EPSV; v0 = s * s;
                s = sqrtf(v1) + EPSV; v1 = s * s;
                s = sqrtf(v2) + EPSV; v2 = s * s;
                s = sqrtf(v3) + EPSV; v3 = s * s;
                __nv_bfloat162 ph;
                ph.x = __float2bfloat16(v0); ph.y = __float2bfloat16(v1);
                *(__nv_bfloat162*)(Hs + rl * 128 + cl) = ph;
                ph.x = __float2bfloat16(v2); ph.y = __float2bfloat16(v3);
                *(__nv_bfloat162*)(Hs + (rl + 8) * 128 + cl) = ph;
            }
        }
        __syncthreads();
        #pragma unroll
        for (int i = 0; i < 8; i++) {
            const int idx = i * 256 + tid;
            const int r = idx >> 4;
            const int sg = idx & 15;
            const size_t gp = (size_t)(row0 + r) * GN + col0 + sg * 8;
            *(uint4*)(ga.Ch + gp) = *(const uint4*)((const char*)Hs + r * 256 + sg * 16);
        }
    }
}

// ---------------------------------------------------------------------------
// qksoft: fused QK^T + dual-temperature softmax (two-pass, no logits array).
// CTA = 128-row strip x full t. Pass A: online max/sums. Pass B: recompute,
// normalize, write amu hi/lo + avarw.
// smem: Q hi/lo resident (32KB) + 2-stage K hi/lo (64KB).
// ---------------------------------------------------------------------------
constexpr uint32_t QS_SMEM = 2 * TILE_B + 2 * 2 * TILE_B + 1024;  // 97KB

__global__ void __launch_bounds__(256, 1) qksoft(
    bf16* __restrict__ amuh, bf16* __restrict__ amul, bf16* __restrict__ avarw,
    const bf16* __restrict__ Qh_, const bf16* __restrict__ Ql_,
    const bf16* __restrict__ Kh_, const bf16* __restrict__ Kl_,
    const float* __restrict__ tau)
{
    extern __shared__ char dsraw[];
    char* dsm = (char*)(((uintptr_t)dsraw + 1023) & ~(uintptr_t)1023);
    const uint32_t base = smem_u32(dsm);
    __shared__ float redm[2][128], red1[2][128], red2[2][128];

    const int tid = threadIdx.x;
    const int wid = tid >> 5;
    const int lane = tid & 31;
    const int wm = wid & 3, wn = wid >> 2;
    const int bh = blockIdx.y;
    const int b = bh >> 4, h = bh & 15;
    const int s0 = blockIdx.x * 128;

    const int lr = tid >> 1;
    const int ls0 = (tid & 1) * 4;
    const size_t qoff = (size_t)(b * S + s0 + lr) * D + h * 64;
    const uint32_t kbase = base + 2 * TILE_B;

    // Q resident load (part of first commit group)
    #pragma unroll
    for (int i = 0; i < 4; i++) {
        const int sg = ls0 + i;
        const uint32_t so = SWZ((uint32_t)(lr * 128 + sg * 16));
        cp16(base + so,          Qh_ + qoff + sg * 8);
        cp16(base + TILE_B + so, Ql_ + qoff + sg * 8);
    }
    auto loadK = [&](int c, int st) {
        const uint32_t sb = kbase + st * (2 * TILE_B);
        const size_t koff = (size_t)(b * S + c * 128 + lr) * D + h * 64;
        #pragma unroll
        for (int i = 0; i < 4; i++) {
            const int sg = ls0 + i;
            const uint32_t so = SWZ((uint32_t)(lr * 128 + sg * 16));
            cp16(sb + so,          Kh_ + koff + sg * 8);
            cp16(sb + TILE_B + so, Kl_ + koff + sg * 8);
        }
    };

    const float tv = tau[0];
    const float l_var = ((0.1f + EPSV) / 64.f + EPSV) / (tv * tv) + EPSV;
    const float invc = rsqrtf(1.f + 0.39269908169872414f * l_var);
    const float scale = 1.f / (8.f * tv);

    const int a_r = wm * 32 + (lane & 15);
    const int a_kseg = (lane >> 4);
    const int b_r = wn * 64 + ((lane >> 4) & 1) * 8 + (lane & 7);
    const int b_kseg = (lane >> 3) & 1;
    const int er = lane >> 2;
    const int ec = (lane & 3) * 2;
    const uint32_t sA = base, sAl = base + TILE_B;

    float m[4], s1[4], s2[4];
    #pragma unroll
    for (int s = 0; s < 4; s++) { m[s] = -1e30f; s1[s] = 0.f; s2[s] = 0.f; }

    float acc[2][8][4];

    // computes acc for chunk at stage st
    auto compute_chunk = [&](int st) {
        #pragma unroll
        for (int mi = 0; mi < 2; mi++)
            #pragma unroll
            for (int ni = 0; ni < 8; ni++)
                #pragma unroll
                for (int q = 0; q < 4; q++) acc[mi][ni][q] = 0.f;
        const uint32_t sB  = kbase + st * (2 * TILE_B);
        const uint32_t sBl = sB + TILE_B;
        #pragma unroll
        for (int ks = 0; ks < 4; ks++) {
            const int k0 = ks * 16;
            uint32_t bh_[16], bl_[16];
            #pragma unroll
            for (int p = 0; p < 4; p++) {
                const uint32_t bo = SWZ((uint32_t)((b_r + p * 16) * 128 +
                                                   (k0 + b_kseg * 8) * 2));
                ldsm4(bh_[4 * p], bh_[4 * p + 1], bh_[4 * p + 2], bh_[4 * p + 3], sB + bo);
                ldsm4(bl_[4 * p], bl_[4 * p + 1], bl_[4 * p + 2], bl_[4 * p + 3], sBl + bo);
            }
            #pragma unroll
            for (int mi = 0; mi < 2; mi++) {
                const uint32_t ao = SWZ((uint32_t)((a_r + mi * 16) * 128 +
                                                   (k0 + a_kseg * 8) * 2));
                uint32_t ah[4], al[4];
                ldsm4(ah[0], ah[1], ah[2], ah[3], sA + ao);
                ldsm4(al[0], al[1], al[2], al[3], sAl + ao);
                #pragma unroll
                for (int ni = 0; ni < 8; ni++) {
                    mma16816(acc[mi][ni], ah, &bh_[ni * 2]);
                    mma16816(acc[mi][ni], ah, &bl_[ni * 2]);
                    mma16816(acc[mi][ni], al, &bh_[ni * 2]);
                }
            }
        }
    };

    // ---------------- PASS A: online stats ----------------
    loadK(0, 0); cp_commit();
    loadK(1, 1); cp_commit();
    for (int c = 0; c < 8; c++) {
        if (c < 7) { cp_wait<1>(); } else { cp_wait<0>(); }
        __syncthreads();
        compute_chunk(c & 1);
        __syncthreads();
        if (c + 2 < 8) { loadK(c + 2, c & 1); cp_commit(); }
        // stats update
        #pragma unroll
        for (int mi = 0; mi < 2; mi++) {
            #pragma unroll
            for (int half = 0; half < 2; half++) {
                const int sl = mi * 2 + half;
                float cmx = -1e30f;
                #pragma unroll
                for (int ni = 0; ni < 8; ni++) {
                    cmx = fmaxf(cmx, fmaxf(acc[mi][ni][half * 2], acc[mi][ni][half * 2 + 1]));
                }
                cmx *= scale;   // scale > 0 (tau = 1): max commutes
                if (cmx > m[sl]) {
                    const float d = m[sl] - cmx;
                    s1[sl] *= __expf(d);
                    s2[sl] *= __expf(d * invc);
                    m[sl] = cmx;
                }
                #pragma unroll
                for (int ni = 0; ni < 8; ni++) {
                    const float v0 = acc[mi][ni][half * 2]     * scale - m[sl];
                    const float v1 = acc[mi][ni][half * 2 + 1] * scale - m[sl];
                    s1[sl] += __expf(v0) + __expf(v1);
                    s2[sl] += __expf(v0 * invc) + __expf(v1 * invc);
                }
            }
        }
    }

    // intra-warp reduce over the 4 lanes sharing each row (xor 1, 2)
    #pragma unroll
    for (int off = 1; off <= 2; off <<= 1) {
        #pragma unroll
        for (int sl = 0; sl < 4; sl++) {
            const float om  = __shfl_xor_sync(0xffffffffu, m[sl],  off);
            const float os1 = __shfl_xor_sync(0xffffffffu, s1[sl], off);
            const float os2 = __shfl_xor_sync(0xffffffffu, s2[sl], off);
            const float nm = fmaxf(m[sl], om);
            s1[sl] = s1[sl] * __expf(m[sl] - nm) + os1 * __expf(om - nm);
            s2[sl] = s2[sl] * __expf((m[sl] - nm) * invc) + os2 * __expf((om - nm) * invc);
            m[sl] = nm;
        }
    }
    // cross-warp (wn halves) via smem
    if ((lane & 3) == 0) {
        #pragma unroll
        for (int sl = 0; sl < 4; sl++) {
            const int row = wm * 32 + (sl >> 1) * 16 + er + (sl & 1) * 8;
            redm[wn][row] = m[sl]; red1[wn][row] = s1[sl]; red2[wn][row] = s2[sl];
        }
    }
    __syncthreads();
    float inv1[4], inv2[4];
    #pragma unroll
    for (int sl = 0; sl < 4; sl++) {
        const int row = wm * 32 + (sl >> 1) * 16 + er + (sl & 1) * 8;
        const float ma = redm[0][row], mb = redm[1][row];
        const float nm = fmaxf(ma, mb);
        const float fs1 = red1[0][row] * __expf(ma - nm) + red1[1][row] * __expf(mb - nm);
        const float fs2 = red2[0][row] * __expf((ma - nm) * invc) +
                          red2[1][row] * __expf((mb - nm) * invc);
        m[sl] = nm;
        inv1[sl] = 1.f / fs1;
        inv2[sl] = 1.f / fs2;
    }
    __syncthreads();

    // ---------------- PASS B: recompute + write ----------------
    loadK(0, 0); cp_commit();
    loadK(1, 1); cp_commit();
    const size_t Lb = (size_t)bh * S * S;
    for (int c = 0; c < 8; c++) {
        if (c < 7) { cp_wait<1>(); } else { cp_wait<0>(); }
        __syncthreads();
        compute_chunk(c & 1);
        __syncthreads();
        if (c + 2 < 8) { loadK(c + 2, c & 1); cp_commit(); }
        #pragma unroll
        for (int mi = 0; mi < 2; mi++) {
            #pragma unroll
            for (int half = 0; half < 2; half++) {
                const int sl = mi * 2 + half;
                const int gr = s0 + wm * 32 + mi * 16 + er + half * 8;
                #pragma unroll
                for (int ni = 0; ni < 8; ni++) {
                    const int gc = c * 128 + wn * 64 + ni * 8 + ec;
                    const float v0 = acc[mi][ni][half * 2]     * scale - m[sl];
                    const float v1 = acc[mi][ni][half * 2 + 1] * scale - m[sl];
                    const float r0 = __expf(v0 * invc) * inv2[sl];
                    const float r1 = __expf(v1 * invc) * inv2[sl];
                    const float mu0 = __expf(v0) * inv1[sl] + r0;
                    const float mu1 = __expf(v1) * inv1[sl] + r1;
                    const float w0 = r0 * (1.f - r0) * l_var;
                    const float w1 = r1 * (1.f - r1) * l_var;
                    const size_t idx = Lb + (size_t)gr * S + gc;
                    store_hl2(amuh, amul, idx, mu0, mu1);
                    store_h2(avarw, idx, w0, w1);
                }
            }
        }
    }
}

// ---------------------------------------------------------------------------
// av_hmma (unchanged from R7)
// ---------------------------------------------------------------------------
constexpr uint32_t VT_B     = 8192;
constexpr uint32_t AV_STAGE = 2 * TILE_B + 2 * VT_B;
constexpr uint32_t AV_SMEM  = 3 * AV_STAGE + 1024;

template<int EPI>
__global__ void __launch_bounds__(256, 1) av_hmma(
    bf16* __restrict__ Yh, bf16* __restrict__ Yl,
    const bf16* __restrict__ Amh, const bf16* __restrict__ Aml,
    const bf16* __restrict__ Vh_, const bf16* __restrict__ Vl_,
    const float* __restrict__ colsum)
{
    extern __shared__ char dsraw[];
    char* dsm = (char*)(((uintptr_t)dsraw + 1023) & ~(uintptr_t)1023);
    const uint32_t base = smem_u32(dsm);

    const int tid = threadIdx.x;
    const int wid = tid >> 5;
    const int lane = tid & 31;
    const int wm = wid & 3, wn = wid >> 2;
    const int bh = blockIdx.y;
    const int b = bh >> 4, h = bh & 15;
    const int s0 = blockIdx.x * 128;

    const int lr = tid >> 1;
    const int ls0 = (tid & 1) * 4;
    const int vr = tid >> 2;
    const int vs0 = (tid & 3) * 2;
    const size_t abase = ((size_t)bh * S + s0 + lr) * S;
    const size_t vbase = (size_t)b * S * D + h * 64 + (size_t)vr * D;

    auto load_chunk = [&](int c, int st) {
        const uint32_t sb = base + st * AV_STAGE;
        const int t0 = c * 64;
        #pragma unroll
        for (int i = 0; i < 4; i++) {
            const int sg = ls0 + i;
            const uint32_t so = SWZ((uint32_t)(lr * 128 + sg * 16));
            cp16(sb + so, Amh + abase + t0 + sg * 8);
            if (EPI == 0) cp16(sb + TILE_B + so, Aml + abase + t0 + sg * 8);
        }
        #pragma unroll
        for (int i = 0; i < 2; i++) {
            const int sg = vs0 + i;
            const uint32_t so = SWZ((uint32_t)(vr * 128 + sg * 16));
            cp16(sb + 2 * TILE_B + so, Vh_ + vbase + (size_t)t0 * D + sg * 8);
            if (EPI == 0)
                cp16(sb + 2 * TILE_B + VT_B + so, Vl_ + vbase + (size_t)t0 * D + sg * 8);
        }
    };

    float acc[2][4][4];
    #pragma unroll
    for (int mi = 0; mi < 2; mi++)
        #pragma unroll
        for (int ni = 0; ni < 4; ni++)
            #pragma unroll
            for (int q = 0; q < 4; q++) acc[mi][ni][q] = 0.f;

    const int a_r = wm * 32 + (lane & 15);
    const int a_kseg = (lane >> 4);
    const int tg = lane >> 3;
    const int tr = lane & 7;

    load_chunk(0, 0); cp_commit();
    load_chunk(1, 1); cp_commit();

    for (int c = 0; c < 16; c++) {
        if (c + 2 < 16) load_chunk(c + 2, (c + 2) % 3);
        cp_commit();
        cp_wait<2>();
        __syncthreads();

        const uint32_t sA  = base + (c % 3) * AV_STAGE;
        const uint32_t sAl = sA + TILE_B;
        const uint32_t sV  = sA + 2 * TILE_B;
        const uint32_t sVl = sV + VT_B;

        #pragma unroll
        for (int ks = 0; ks < 4; ks++) {
            const int k0 = ks * 16;
            uint32_t bh_[8], bl_[8];
            #pragma unroll
            for (int p = 0; p < 2; p++) {
                const uint32_t bo = SWZ((uint32_t)(
                    (k0 + (tg & 1) * 8 + tr) * 128 +
                    (wn * 32 + p * 16 + (tg >> 1) * 8) * 2));
                ldsm4t(bh_[4 * p], bh_[4 * p + 1], bh_[4 * p + 2], bh_[4 * p + 3], sV + bo);
                if (EPI == 0)
                    ldsm4t(bl_[4 * p], bl_[4 * p + 1], bl_[4 * p + 2], bl_[4 * p + 3], sVl + bo);
            }
            #pragma unroll
            for (int mi = 0; mi < 2; mi++) {
                const uint32_t ao = SWZ((uint32_t)((a_r + mi * 16) * 128 +
                                                   (k0 + a_kseg * 8) * 2));
                uint32_t ah[4], al[4];
                ldsm4(ah[0], ah[1], ah[2], ah[3], sA + ao);
                if (EPI == 0) ldsm4(al[0], al[1], al[2], al[3], sAl + ao);
                #pragma unroll
                for (int ni = 0; ni < 4; ni++) {
                    mma16816(acc[mi][ni], ah, &bh_[ni * 2]);
                    if (EPI == 0) {
                        mma16816(acc[mi][ni], ah, &bl_[ni * 2]);
                        mma16816(acc[mi][ni], al, &bh_[ni * 2]);
                    }
                }
            }
        }
        __syncthreads();
    }

    const int er = lane >> 2;
    const int ec = (lane & 3) * 2;
    #pragma unroll
    for (int mi = 0; mi < 2; mi++) {
        #pragma unroll
        for (int ni = 0; ni < 4; ni++) {
            const int gr = s0 + wm * 32 + mi * 16 + er;
            const int gc = wn * 32 + ni * 8 + ec;
            float v0 = acc[mi][ni][0], v1 = acc[mi][ni][1];
            float v2 = acc[mi][ni][2], v3 = acc[mi][ni][3];
            const size_t idx = (size_t)(b * S + gr) * D + h * 64 + gc;
            if (EPI == 1) {
                const float c0 = C0V * colsum[b * D + h * 64 + gc];
                const float c1 = C0V * colsum[b * D + h * 64 + gc + 1];
                v0 += c0; v1 += c1; v2 += c0; v3 += c1;
                float s;
                s = sqrtf(v0 + EPSV) + EPSV; v0 = s * s;
                s = sqrtf(v1 + EPSV) + EPSV; v1 = s * s;
                s = sqrtf(v2 + EPSV) + EPSV; v2 = s * s;
                s = sqrtf(v3 + EPSV) + EPSV; v3 = s * s;
                store_h2(Yh, idx, v0, v1);
                store_h2(Yh, idx + 8 * (size_t)D, v2, v3);
            } else {
                store_hl2(Yh, Yl, idx, v0, v1);
                store_hl2(Yh, Yl, idx + 8 * (size_t)D, v2, v3);
            }
        }
    }
}

// ---------------------------------------------------------------------------
extern "C" void kernel_launch(void* const* d_in, const int* in_sizes, int n_in,
                              void* d_out, int out_size)
{
    const float* q_loc   = (const float*)d_in[0];
    const float* k_loc   = (const float*)d_in[2];
    const float* v_loc   = (const float*)d_in[4];
    const float* v_scale = (const float*)d_in[5];
    const float* Wq = (const float*)d_in[6];
    const float* bq = (const float*)d_in[7];
    const float* Wk = (const float*)d_in[8];
    const float* bk = (const float*)d_in[9];
    const float* Wv = (const float*)d_in[10];
    const float* bv = (const float*)d_in[11];
    const float* Wo = (const float*)d_in[12];
    const float* bo = (const float*)d_in[13];
    const float* tau = (const float*)d_in[14];

    float* out_loc   = (float*)d_out;
    float* out_scale = (float*)d_out + PROJ;

    float* cs;
    cudaGetSymbolAddress((void**)&cs, g_colsum);
    bf16 *amuh, *amul, *avarw;
    cudaGetSymbolAddress((void**)&amuh, g_amuh); cudaGetSymbolAddress((void**)&amul, g_amul);
    cudaGetSymbolAddress((void**)&avarw, g_avarw);
    bf16 *qh,*ql,*kh,*kl,*vh,*vl,*vsh;
    cudaGetSymbolAddress((void**)&qh, g_qh);   cudaGetSymbolAddress((void**)&ql, g_ql);
    cudaGetSymbolAddress((void**)&kh, g_kh);   cudaGetSymbolAddress((void**)&kl, g_kl);
    cudaGetSymbolAddress((void**)&vh, g_vh);   cudaGetSymbolAddress((void**)&vl, g_vl);
    cudaGetSymbolAddress((void**)&vsh, g_vsh);
    bf16 *qmh,*qml,*kmh,*kml,*vmh,*vml,*vvh,*ymh,*yml,*pph;
    cudaGetSymbolAddress((void**)&qmh, g_qmh); cudaGetSymbolAddress((void**)&qml, g_qml);
    cudaGetSymbolAddress((void**)&kmh, g_kmh); cudaGetSymbolAddress((void**)&kml, g_kml);
    cudaGetSymbolAddress((void**)&vmh, g_vmh); cudaGetSymbolAddress((void**)&vml, g_vml);
    cudaGetSymbolAddress((void**)&vvh, g_vvh);
    cudaGetSymbolAddress((void**)&ymh, g_ymh); cudaGetSymbolAddress((void**)&yml, g_yml);
    cudaGetSymbolAddress((void**)&pph, g_pph);
    bf16 *wqh,*wql,*wkh,*wkl,*wvh,*wvl,*wvsh,*woh,*wol,*wosh;
    cudaGetSymbolAddress((void**)&wqh, g_wqh);   cudaGetSymbolAddress((void**)&wql, g_wql);
    cudaGetSymbolAddress((void**)&wkh, g_wkh);   cudaGetSymbolAddress((void**)&wkl, g_wkl);
    cudaGetSymbolAddress((void**)&wvh, g_wvh);   cudaGetSymbolAddress((void**)&wvl, g_wvl);
    cudaGetSymbolAddress((void**)&wvsh, g_wvsh);
    cudaGetSymbolAddress((void**)&woh, g_woh);   cudaGetSymbolAddress((void**)&wol, g_wol);
    cudaGetSymbolAddress((void**)&wosh, g_wosh);

    cudaFuncSetAttribute(gemm_mma_b,  cudaFuncAttributeMaxDynamicSharedMemorySize, GSMEM);
    cudaFuncSetAttribute(qksoft,      cudaFuncAttributeMaxDynamicSharedMemorySize, QS_SMEM);
    cudaFuncSetAttribute(av_hmma<0>,  cudaFuncAttributeMaxDynamicSharedMemorySize, AV_SMEM);
    cudaFuncSetAttribute(av_hmma<1>,  cudaFuncAttributeMaxDynamicSharedMemorySize, AV_SMEM);

    // hi/lo conversion (variance-chain inputs single-plane)
    CvtParams P;
    const int PN = (int)PROJ, WN = (int)WSZ;
    P.src[0] = q_loc;   P.hi[0] = qh;   P.lo[0] = ql;      P.n[0] = PN; P.sq[0] = 0;
    P.src[1] = k_loc;   P.hi[1] = kh;   P.lo[1] = kl;      P.n[1] = PN; P.sq[1] = 0;
    P.src[2] = v_loc;   P.hi[2] = vh;   P.lo[2] = vl;      P.n[2] = PN; P.sq[2] = 0;
    P.src[3] = v_scale; P.hi[3] = vsh;  P.lo[3] = nullptr; P.n[3] = PN; P.sq[3] = 1;
    P.src[4] = Wq;      P.hi[4] = wqh;  P.lo[4] = wql;     P.n[4] = WN; P.sq[4] = 0;
    P.src[5] = Wk;      P.hi[5] = wkh;  P.lo[5] = wkl;     P.n[5] = WN; P.sq[5] = 0;
    P.src[6] = Wv;      P.hi[6] = wvh;  P.lo[6] = wvl;     P.n[6] = WN; P.sq[6] = 0;
    P.src[7] = Wv;      P.hi[7] = wvsh; P.lo[7] = nullptr; P.n[7] = WN; P.sq[7] = 1;
    P.src[8] = Wo;      P.hi[8] = woh;  P.lo[8] = wol;     P.n[8] = WN; P.sq[8] = 0;
    P.src[9] = Wo;      P.hi[9] = wosh; P.lo[9] = nullptr; P.n[9] = WN; P.sq[9] = 1;
    P.cs = cs;
    convert_all<<<dim3(PN / 1024, 10), 256>>>(P);

    // batched projections: qm, km, vm (3-pass, hi/lo out) + vvar (1-pass)
    GemmBatch bp;
    bp.a[0] = { qh,  ql,      wqh,  wql,    bq,      nullptr, qmh, qml,     3, 3 };
    bp.a[1] = { kh,  kl,      wkh,  wkl,    bk,      nullptr, kmh, kml,     3, 3 };
    bp.a[2] = { vh,  vl,      wvh,  wvl,    bv,      nullptr, vmh, vml,     3, 3 };
    bp.a[3] = { vsh, nullptr, wvsh, nullptr,nullptr, nullptr, vvh, nullptr, 5, 1 };
    gemm_mma_b<<<dim3(GN / 128, BS / 128, 4), 256, GSMEM>>>(bp);

    // colsum over t of vvar
    colsum_kernel<<<dim3(B * D / 256, S / 64), 256>>>(cs, vvh);

    // fused QK + dual softmax (no logits array)
    qksoft<<<dim3(S / 128, B * H), 256, QS_SMEM>>>(amuh, amul, avarw,
                                                   qmh, qml, kmh, kml, tau);

    // AV (mean 3-pass, var 1-pass + colsum fold)
    av_hmma<0><<<dim3(S / 128, B * H), 256, AV_SMEM>>>(ymh, yml, amuh, amul, vmh, vml, nullptr);
    av_hmma<1><<<dim3(S / 128, B * H), 256, AV_SMEM>>>(pph, nullptr, avarw, nullptr, vvh, nullptr, cs);

    // batched output projections: out_loc (3-pass) + out_scale (1-pass)
    GemmBatch bo2;
    bo2.a[0] = { ymh, yml,     woh,  wol,    bo,      out_loc,   nullptr, nullptr, 0, 3 };
    bo2.a[1] = { pph, nullptr, wosh, nullptr,nullptr, out_scale, nullptr, nullptr, 2, 1 };
    bo2.a[2] = bo2.a[0];
    bo2.a[3] = bo2.a[0];
    gemm_mma_b<<<dim3(GN / 128, BS / 128, 2), 256, GSMEM>>>(bo2);
}

// round 9
// speedup vs baseline: 1.0741x; 1.0741x over previous
#include <cuda_runtime.h>
#include <cuda_bf16.h>
#include <math.h>
#include <stdint.h>

#define EPSV 1e-6f
using bf16 = __nv_bfloat16;

constexpr int B = 2, S = 1024, D = 1024, H = 16, HD = 64;
constexpr int BS = B * S;                         // 2048
constexpr size_t PROJ = (size_t)BS * D;           // 2M
constexpr size_t ATTN = (size_t)B * H * S * S;    // 32M
constexpr size_t WSZ  = (size_t)D * D;            // 1M
#define C0V (1e-4f + EPSV)

// ---------------- scratch ---------------------------------------------------
__device__ float g_logits[ATTN];
__device__ float g_colsum[B * D];
__device__ bf16 g_amuh[ATTN], g_amul[ATTN], g_avarw[ATTN];
__device__ bf16 g_qh[PROJ], g_ql[PROJ], g_kh[PROJ], g_kl[PROJ];
__device__ bf16 g_vh[PROJ], g_vl[PROJ], g_vsh[PROJ];
__device__ bf16 g_qmh[PROJ], g_qml[PROJ], g_kmh[PROJ], g_kml[PROJ];
__device__ bf16 g_vmh[PROJ], g_vml[PROJ], g_vvh[PROJ];
__device__ bf16 g_ymh[PROJ], g_yml[PROJ], g_pph[PROJ];
__device__ bf16 g_wqh[WSZ], g_wql[WSZ], g_wkh[WSZ], g_wkl[WSZ];
__device__ bf16 g_wvh[WSZ], g_wvl[WSZ], g_wvsh[WSZ];
__device__ bf16 g_woh[WSZ], g_wol[WSZ], g_wosh[WSZ];

// ---------------- helpers ---------------------------------------------------
__device__ __forceinline__ uint32_t smem_u32(const void* p) {
    uint32_t a;
    asm("{ .reg .u64 t; cvta.to.shared.u64 t, %1; cvt.u32.u64 %0, t; }" : "=r"(a) : "l"(p));
    return a;
}
#define SWZ(o) ((o) ^ (((o) >> 3) & 0x70))

__device__ __forceinline__ void cp16(uint32_t dst, const void* src) {
    asm volatile("cp.async.cg.shared.global [%0], [%1], 16;" :: "r"(dst), "l"(src));
}
__device__ __forceinline__ void cp_commit() {
    asm volatile("cp.async.commit_group;" ::: "memory");
}
template<int N>
__device__ __forceinline__ void cp_wait() {
    asm volatile("cp.async.wait_group %0;" :: "n"(N) : "memory");
}
__device__ __forceinline__ void ldsm4(uint32_t& r0, uint32_t& r1, uint32_t& r2, uint32_t& r3,
                                      uint32_t addr) {
    asm volatile("ldmatrix.sync.aligned.m8n8.x4.shared.b16 {%0,%1,%2,%3}, [%4];"
                 : "=r"(r0), "=r"(r1), "=r"(r2), "=r"(r3) : "r"(addr));
}
__device__ __forceinline__ void ldsm4t(uint32_t& r0, uint32_t& r1, uint32_t& r2, uint32_t& r3,
                                       uint32_t addr) {
    asm volatile("ldmatrix.sync.aligned.m8n8.x4.trans.shared.b16 {%0,%1,%2,%3}, [%4];"
                 : "=r"(r0), "=r"(r1), "=r"(r2), "=r"(r3) : "r"(addr));
}
__device__ __forceinline__ void mma16816(float* d, const uint32_t* a, const uint32_t* b) {
    asm volatile(
        "mma.sync.aligned.m16n8k16.row.col.f32.bf16.bf16.f32 "
        "{%0,%1,%2,%3}, {%4,%5,%6,%7}, {%8,%9}, {%0,%1,%2,%3};"
        : "+f"(d[0]), "+f"(d[1]), "+f"(d[2]), "+f"(d[3])
        : "r"(a[0]), "r"(a[1]), "r"(a[2]), "r"(a[3]), "r"(b[0]), "r"(b[1]));
}
__device__ __forceinline__ void split2(float v, bf16& h, bf16& l) {
    h = __float2bfloat16(v);
    l = __float2bfloat16(v - __bfloat162float(h));
}
__device__ __forceinline__ void store_hl2(bf16* Ph, bf16* Pl, size_t idx, float v0, float v1) {
    bf16 h0, l0, h1, l1;
    split2(v0, h0, l0); split2(v1, h1, l1);
    __nv_bfloat162 ph; ph.x = h0; ph.y = h1;
    __nv_bfloat162 pl; pl.x = l0; pl.y = l1;
    *(__nv_bfloat162*)(Ph + idx) = ph;
    *(__nv_bfloat162*)(Pl + idx) = pl;
}
__device__ __forceinline__ void store_h2(bf16* Ph, size_t idx, float v0, float v1) {
    __nv_bfloat162 ph;
    ph.x = __float2bfloat16(v0); ph.y = __float2bfloat16(v1);
    *(__nv_bfloat162*)(Ph + idx) = ph;
}

// ---------------------------------------------------------------------------
// convert_all
// ---------------------------------------------------------------------------
struct CvtParams {
    const float* src[10];
    bf16* hi[10];
    bf16* lo[10];
    int n[10];
    int sq[10];
    float* cs;
};

__global__ void __launch_bounds__(256) convert_all(CvtParams P) {
    if (blockIdx.y == 0 && blockIdx.x == 0) {
        for (int i = threadIdx.x; i < B * D; i += 256) P.cs[i] = 0.f;
    }
    const int r = blockIdx.y;
    const int i4 = (blockIdx.x * 256 + threadIdx.x) * 4;
    if (i4 >= P.n[r]) return;
    float4 v = *(const float4*)(P.src[r] + i4);
    if (P.sq[r]) { v.x *= v.x; v.y *= v.y; v.z *= v.z; v.w *= v.w; }
    if (P.lo[r]) {
        store_hl2(P.hi[r], P.lo[r], i4, v.x, v.y);
        store_hl2(P.hi[r], P.lo[r], i4 + 2, v.z, v.w);
    } else {
        store_h2(P.hi[r], i4, v.x, v.y);
        store_h2(P.hi[r], i4 + 2, v.z, v.w);
    }
}

// ---------------------------------------------------------------------------
// colsum
// ---------------------------------------------------------------------------
__global__ void __launch_bounds__(256) colsum_kernel(float* cs, const bf16* vv) {
    const int d = blockIdx.x * 256 + threadIdx.x;
    const int b = d >> 10, dd = d & 1023;
    const int t0 = blockIdx.y * 64;
    const bf16* p = vv + (size_t)b * S * D + (size_t)t0 * D + dd;
    float s = 0.f;
    #pragma unroll 8
    for (int t = 0; t < 64; t++) s += __bfloat162float(p[(size_t)t * D]);
    atomicAdd(cs + d, s);
}

// ---------------------------------------------------------------------------
// Batched projection-shaped GEMM (identical to R7)
// ---------------------------------------------------------------------------
constexpr int GK = 1024;
constexpr int GN = 1024;
constexpr uint32_t TILE_B  = 16384;
constexpr uint32_t STAGE_B = 4 * TILE_B;
constexpr uint32_t GSMEM   = 3 * STAGE_B + 1024;

struct GemmArgs {
    const bf16 *Ah, *Al, *Bh, *Bl;
    const float* bias;
    float* Cf;
    bf16 *Ch, *Cl;
    int epi;
    int passes;
};
struct GemmBatch { GemmArgs a[4]; };

__global__ void __launch_bounds__(256, 1) gemm_mma_b(GemmBatch bat)
{
    extern __shared__ char dsraw[];
    char* dsm = (char*)(((uintptr_t)dsraw + 1023) & ~(uintptr_t)1023);
    const uint32_t base = smem_u32(dsm);

    const GemmArgs ga = bat.a[blockIdx.z];
    const bool p3 = (ga.passes == 3);

    const int tid  = threadIdx.x;
    const int wid  = tid >> 5;
    const int lane = tid & 31;
    const int wm = wid & 3;
    const int wn = wid >> 2;
    const int row0 = blockIdx.y * 128;
    const int col0 = blockIdx.x * 128;

    const int lr = tid >> 1;
    const int ls0 = (tid & 1) * 4;
    const size_t aoff = (size_t)(row0 + lr) * GK;
    const size_t boff = (size_t)(col0 + lr) * GK;

    auto load_chunk = [&](int c, int st) {
        const uint32_t sb = base + st * STAGE_B;
        const int k0 = c * 64;
        #pragma unroll
        for (int i = 0; i < 4; i++) {
            const int sg = ls0 + i;
            const uint32_t so = SWZ((uint32_t)(lr * 128 + sg * 16));
            const size_t gai = aoff + k0 + sg * 8;
            const size_t gbi = boff + k0 + sg * 8;
            cp16(sb + so,              ga.Ah + gai);
            cp16(sb + 2 * TILE_B + so, ga.Bh + gbi);
            if (p3) {
                cp16(sb + TILE_B + so,     ga.Al + gai);
                cp16(sb + 3 * TILE_B + so, ga.Bl + gbi);
            }
        }
    };

    float acc[2][8][4];
    #pragma unroll
    for (int mi = 0; mi < 2; mi++)
        #pragma unroll
        for (int ni = 0; ni < 8; ni++)
            #pragma unroll
            for (int q = 0; q < 4; q++) acc[mi][ni][q] = 0.f;

    const int a_r = wm * 32 + (lane & 15);
    const int a_kseg = (lane >> 4);
    const int b_r = wn * 64 + ((lane >> 4) & 1) * 8 + (lane & 7);
    const int b_kseg = (lane >> 3) & 1;

    load_chunk(0, 0); cp_commit();
    load_chunk(1, 1); cp_commit();

    for (int c = 0; c < 16; c++) {
        if (c + 2 < 16) load_chunk(c + 2, (c + 2) % 3);
        cp_commit();
        cp_wait<2>();
        __syncthreads();

        const uint32_t sA = base + (c % 3) * STAGE_B;
        const uint32_t sB = sA + 2 * TILE_B;

        #pragma unroll
        for (int ks = 0; ks < 4; ks++) {
            const int k0 = ks * 16;
            uint32_t bh_[16], bl_[16];
            #pragma unroll
            for (int p = 0; p < 4; p++) {
                const uint32_t bo = SWZ((uint32_t)((b_r + p * 16) * 128 +
                                                   (k0 + b_kseg * 8) * 2));
                ldsm4(bh_[4 * p], bh_[4 * p + 1], bh_[4 * p + 2], bh_[4 * p + 3], sB + bo);
                if (p3)
                    ldsm4(bl_[4 * p], bl_[4 * p + 1], bl_[4 * p + 2], bl_[4 * p + 3],
                          sB + TILE_B + bo);
            }
            #pragma unroll
            for (int mi = 0; mi < 2; mi++) {
                const uint32_t ao = SWZ((uint32_t)((a_r + mi * 16) * 128 +
                                                   (k0 + a_kseg * 8) * 2));
                uint32_t ah[4], al[4];
                ldsm4(ah[0], ah[1], ah[2], ah[3], sA + ao);
                if (p3) ldsm4(al[0], al[1], al[2], al[3], sA + TILE_B + ao);
                #pragma unroll
                for (int ni = 0; ni < 8; ni++) {
                    mma16816(acc[mi][ni], ah, &bh_[ni * 2]);
                    if (p3) {
                        mma16816(acc[mi][ni], ah, &bl_[ni * 2]);
                        mma16816(acc[mi][ni], al, &bh_[ni * 2]);
                    }
                }
            }
        }
        __syncthreads();
    }

    const int er = lane >> 2;
    const int ec = (lane & 3) * 2;
    const int epi = ga.epi;

    if (epi <= 2) {
        #pragma unroll
        for (int mi = 0; mi < 2; mi++) {
            #pragma unroll
            for (int ni = 0; ni < 8; ni++) {
                const int gr = row0 + wm * 32 + mi * 16 + er;
                const int gc = col0 + wn * 64 + ni * 8 + ec;
                float v0 = acc[mi][ni][0], v1 = acc[mi][ni][1];
                float v2 = acc[mi][ni][2], v3 = acc[mi][ni][3];
                if (epi == 0) {
                    const float b0 = ga.bias[gc], b1 = ga.bias[gc + 1];
                    v0 += b0; v1 += b1; v2 += b0; v3 += b1;
                } else {
                    v0 = sqrtf(v0); v1 = sqrtf(v1); v2 = sqrtf(v2); v3 = sqrtf(v3);
                }
                float2 w0 = {v0, v1}, w1 = {v2, v3};
                *(float2*)(ga.Cf + (size_t)gr * GN + gc)       = w0;
                *(float2*)(ga.Cf + (size_t)(gr + 8) * GN + gc) = w1;
            }
        }
    } else if (epi == 3) {
        bf16* Hs = (bf16*)dsm;
        bf16* Ls = (bf16*)(dsm + 32768);
        #pragma unroll
        for (int mi = 0; mi < 2; mi++) {
            #pragma unroll
            for (int ni = 0; ni < 8; ni++) {
                const int rl = wm * 32 + mi * 16 + er;
                const int cl = wn * 64 + ni * 8 + ec;
                float v0 = acc[mi][ni][0], v1 = acc[mi][ni][1];
                float v2 = acc[mi][ni][2], v3 = acc[mi][ni][3];
                const float b0 = ga.bias[col0 + cl], b1 = ga.bias[col0 + cl + 1];
                v0 += b0; v1 += b1; v2 += b0; v3 += b1;
                bf16 h0, l0, h1, l1;
                split2(v0, h0, l0); split2(v1, h1, l1);
                __nv_bfloat162 ph; ph.x = h0; ph.y = h1;
                __nv_bfloat162 pl; pl.x = l0; pl.y = l1;
                *(__nv_bfloat162*)(Hs + rl * 128 + cl) = ph;
                *(__nv_bfloat162*)(Ls + rl * 128 + cl) = pl;
                split2(v2, h0, l0); split2(v3, h1, l1);
                ph.x = h0; ph.y = h1; pl.x = l0; pl.y = l1;
                *(__nv_bfloat162*)(Hs + (rl + 8) * 128 + cl) = ph;
                *(__nv_bfloat162*)(Ls + (rl + 8) * 128 + cl) = pl;
            }
        }
        __syncthreads();
        #pragma unroll
        for (int i = 0; i < 8; i++) {
            const int idx = i * 256 + tid;
            const int r = idx >> 4;
            const int sg = idx & 15;
            const size_t gp = (size_t)(row0 + r) * GN + col0 + sg * 8;
            *(uint4*)(ga.Ch + gp) = *(const uint4*)((const char*)Hs + r * 256 + sg * 16);
            *(uint4*)(ga.Cl + gp) = *(const uint4*)((const char*)Ls + r * 256 + sg * 16);
        }
    } else {   // epi == 5
        bf16* Hs = (bf16*)dsm;
        #pragma unroll
        for (int mi = 0; mi < 2; mi++) {
            #pragma unroll
            for (int ni = 0; ni < 8; ni++) {
                const int rl = wm * 32 + mi * 16 + er;
                const int cl = wn * 64 + ni * 8 + ec;
                float v0 = acc[mi][ni][0], v1 = acc[mi][ni][1];
                float v2 = acc[mi][ni][2], v3 = acc[mi][ni][3];
                float s;
                s = sqrtf(v0) + EPSV; v0 = s * s;
                s = sqrtf(v1) + EPSV; v1 = s * s;
                s = sqrtf(v2) + EPSV; v2 = s * s;
                s = sqrtf(v3) + EPSV; v3 = s * s;
                __nv_bfloat162 ph;
                ph.x = __float2bfloat16(v0); ph.y = __float2bfloat16(v1);
                *(__nv_bfloat162*)(Hs + rl * 128 + cl) = ph;
                ph.x = __float2bfloat16(v2); ph.y = __float2bfloat16(v3);
                *(__nv_bfloat162*)(Hs + (rl + 8) * 128 + cl) = ph;
            }
        }
        __syncthreads();
        #pragma unroll
        for (int i = 0; i < 8; i++) {
            const int idx = i * 256 + tid;
            const int r = idx >> 4;
            const int sg = idx & 15;
            const size_t gp = (size_t)(row0 + r) * GN + col0 + sg * 8;
            *(uint4*)(ga.Ch + gp) = *(const uint4*)((const char*)Hs + r * 256 + sg * 16);
        }
    }
}

// ---------------------------------------------------------------------------
// qk_hmma: register-lean variant, 2 CTAs/SM target
// ---------------------------------------------------------------------------
constexpr uint32_t QK_SMEM = 4 * TILE_B + 1024;

__global__ void __launch_bounds__(256, 2) qk_hmma(
    float* __restrict__ L,
    const bf16* __restrict__ Qh_, const bf16* __restrict__ Ql_,
    const bf16* __restrict__ Kh_, const bf16* __restrict__ Kl_,
    const float* __restrict__ tau)
{
    extern __shared__ char dsraw[];
    char* dsm = (char*)(((uintptr_t)dsraw + 1023) & ~(uintptr_t)1023);
    const uint32_t base = smem_u32(dsm);

    const int tid = threadIdx.x;
    const int wid = tid >> 5;
    const int lane = tid & 31;
    const int wm = wid & 3, wn = wid >> 2;
    const int bh = blockIdx.z;
    const int b = bh >> 4, h = bh & 15;
    const int s0 = blockIdx.y * 128, t0 = blockIdx.x * 128;

    const int lr = tid >> 1;
    const int ls0 = (tid & 1) * 4;
    const size_t qoff = (size_t)(b * S + s0 + lr) * D + h * 64;
    const size_t koff = (size_t)(b * S + t0 + lr) * D + h * 64;
    #pragma unroll
    for (int i = 0; i < 4; i++) {
        const int sg = ls0 + i;
        const uint32_t so = SWZ((uint32_t)(lr * 128 + sg * 16));
        cp16(base + so,              Qh_ + qoff + sg * 8);
        cp16(base + TILE_B + so,     Ql_ + qoff + sg * 8);
        cp16(base + 2 * TILE_B + so, Kh_ + koff + sg * 8);
        cp16(base + 3 * TILE_B + so, Kl_ + koff + sg * 8);
    }
    cp_commit();
    cp_wait<0>();
    __syncthreads();

    float acc[2][8][4];
    #pragma unroll
    for (int mi = 0; mi < 2; mi++)
        #pragma unroll
        for (int ni = 0; ni < 8; ni++)
            #pragma unroll
            for (int q = 0; q < 4; q++) acc[mi][ni][q] = 0.f;

    const int a_r = wm * 32 + (lane & 15);
    const int a_kseg = (lane >> 4);
    const int b_r = wn * 64 + ((lane >> 4) & 1) * 8 + (lane & 7);
    const int b_kseg = (lane >> 3) & 1;
    const uint32_t sA = base, sAl = base + TILE_B;
    const uint32_t sB = base + 2 * TILE_B, sBl = base + 3 * TILE_B;

    #pragma unroll
    for (int ks = 0; ks < 4; ks++) {
        const int k0 = ks * 16;
        // A fragments for both mi (held across the p loop)
        uint32_t ah[2][4], al[2][4];
        #pragma unroll
        for (int mi = 0; mi < 2; mi++) {
            const uint32_t ao = SWZ((uint32_t)((a_r + mi * 16) * 128 + (k0 + a_kseg * 8) * 2));
            ldsm4(ah[mi][0], ah[mi][1], ah[mi][2], ah[mi][3], sA + ao);
            ldsm4(al[mi][0], al[mi][1], al[mi][2], al[mi][3], sAl + ao);
        }
        #pragma unroll
        for (int p = 0; p < 4; p++) {
            const uint32_t bo = SWZ((uint32_t)((b_r + p * 16) * 128 + (k0 + b_kseg * 8) * 2));
            uint32_t bh4[4], bl4[4];
            ldsm4(bh4[0], bh4[1], bh4[2], bh4[3], sB + bo);
            ldsm4(bl4[0], bl4[1], bl4[2], bl4[3], sBl + bo);
            #pragma unroll
            for (int mi = 0; mi < 2; mi++) {
                #pragma unroll
                for (int nj = 0; nj < 2; nj++) {
                    float* a4 = acc[mi][p * 2 + nj];
                    mma16816(a4, ah[mi], &bh4[nj * 2]);
                    mma16816(a4, ah[mi], &bl4[nj * 2]);
                    mma16816(a4, al[mi], &bh4[nj * 2]);
                }
            }
        }
    }

    const float scale = 1.f / (8.f * tau[0]);
    const int er = lane >> 2;
    const int ec = (lane & 3) * 2;
    float* Lb = L + (size_t)bh * S * S;
    #pragma unroll
    for (int mi = 0; mi < 2; mi++) {
        #pragma unroll
        for (int ni = 0; ni < 8; ni++) {
            const int gr = s0 + wm * 32 + mi * 16 + er;
            const int gc = t0 + wn * 64 + ni * 8 + ec;
            float2 w0 = {acc[mi][ni][0] * scale, acc[mi][ni][1] * scale};
            float2 w1 = {acc[mi][ni][2] * scale, acc[mi][ni][3] * scale};
            *(float2*)(Lb + (size_t)gr * S + gc)       = w0;
            *(float2*)(Lb + (size_t)(gr + 8) * S + gc) = w1;
        }
    }
}

// ---------------------------------------------------------------------------
// softmax (identical to R7)
// ---------------------------------------------------------------------------
__global__ void __launch_bounds__(256) softmax_kernel(
    bf16* __restrict__ amuh, bf16* __restrict__ amul, bf16* __restrict__ avarw,
    const float* __restrict__ logits, const float* __restrict__ tau)
{
    __shared__ float shm[8], sh1[8], sh2[8];
    const int tid = threadIdx.x;
    const size_t row = blockIdx.x;
    const float4 v = ((const float4*)(logits + row * (size_t)S))[tid];

    float m = fmaxf(fmaxf(v.x, v.y), fmaxf(v.z, v.w));
    #pragma unroll
    for (int o = 16; o; o >>= 1) m = fmaxf(m, __shfl_xor_sync(0xffffffffu, m, o));
    if ((tid & 31) == 0) shm[tid >> 5] = m;
    __syncthreads();
    m = shm[tid & 7];
    #pragma unroll
    for (int o = 4; o; o >>= 1) m = fmaxf(m, __shfl_xor_sync(0xffffffffu, m, o));

    const float tv = tau[0];
    const float l_var = ((0.1f + EPSV) / 64.f + EPSV) / (tv * tv) + EPSV;
    const float invc = rsqrtf(1.f + 0.39269908169872414f * l_var);

    float4 e1, e2;
    e1.x = expf(v.x - m); e1.y = expf(v.y - m); e1.z = expf(v.z - m); e1.w = expf(v.w - m);
    e2.x = expf((v.x - m) * invc); e2.y = expf((v.y - m) * invc);
    e2.z = expf((v.z - m) * invc); e2.w = expf((v.w - m) * invc);

    float s1 = e1.x + e1.y + e1.z + e1.w;
    float s2 = e2.x + e2.y + e2.z + e2.w;
    #pragma unroll
    for (int o = 16; o; o >>= 1) {
        s1 += __shfl_xor_sync(0xffffffffu, s1, o);
        s2 += __shfl_xor_sync(0xffffffffu, s2, o);
    }
    if ((tid & 31) == 0) { sh1[tid >> 5] = s1; sh2[tid >> 5] = s2; }
    __syncthreads();
    s1 = sh1[tid & 7]; s2 = sh2[tid & 7];
    #pragma unroll
    for (int o = 4; o; o >>= 1) {
        s1 += __shfl_xor_sync(0xffffffffu, s1, o);
        s2 += __shfl_xor_sync(0xffffffffu, s2, o);
    }

    const float r1 = 1.f / s1, r2 = 1.f / s2;
    float mu[4], w[4];
    {
        float t, r;
        t = e1.x * r1; r = e2.x * r2; mu[0] = t + r; w[0] = r * (1.f - r) * l_var;
        t = e1.y * r1; r = e2.y * r2; mu[1] = t + r; w[1] = r * (1.f - r) * l_var;
        t = e1.z * r1; r = e2.z * r2; mu[2] = t + r; w[2] = r * (1.f - r) * l_var;
        t = e1.w * r1; r = e2.w * r2; mu[3] = t + r; w[3] = r * (1.f - r) * l_var;
    }
    const size_t o0 = row * (size_t)S + tid * 4;
    store_hl2(amuh, amul, o0,     mu[0], mu[1]);
    store_hl2(amuh, amul, o0 + 2, mu[2], mu[3]);
    store_h2(avarw, o0,     w[0], w[1]);
    store_h2(avarw, o0 + 2, w[2], w[3]);
}

// ---------------------------------------------------------------------------
// av_hmma_b: batched (z: mean-path epi0 3-pass, var-path epi1 1-pass)
// 2-stage pipeline, register-lean, 2 CTAs/SM target
// ---------------------------------------------------------------------------
constexpr uint32_t VT_B     = 8192;
constexpr uint32_t AV_STAGE = 2 * TILE_B + 2 * VT_B;       // 48KB
constexpr uint32_t AV_SMEM  = 2 * AV_STAGE + 1024;         // ~97KB -> 2 CTAs

struct AvArgs {
    bf16 *Yh, *Yl;
    const bf16 *Amh, *Aml, *Vh, *Vl;
    const float* cs;
    int epi;
};
struct AvBatch { AvArgs a[2]; };

__global__ void __launch_bounds__(256, 2) av_hmma_b(AvBatch bat)
{
    extern __shared__ char dsraw[];
    char* dsm = (char*)(((uintptr_t)dsraw + 1023) & ~(uintptr_t)1023);
    const uint32_t base = smem_u32(dsm);

    const AvArgs ga = bat.a[blockIdx.z];
    const bool p3 = (ga.epi == 0);

    const int tid = threadIdx.x;
    const int wid = tid >> 5;
    const int lane = tid & 31;
    const int wm = wid & 3, wn = wid >> 2;
    const int bh = blockIdx.y;
    const int b = bh >> 4, h = bh & 15;
    const int s0 = blockIdx.x * 128;

    const int lr = tid >> 1;
    const int ls0 = (tid & 1) * 4;
    const int vr = tid >> 2;
    const int vs0 = (tid & 3) * 2;
    const size_t abase = ((size_t)bh * S + s0 + lr) * S;
    const size_t vbase = (size_t)b * S * D + h * 64 + (size_t)vr * D;

    auto load_chunk = [&](int c, int st) {
        const uint32_t sb = base + st * AV_STAGE;
        const int t0 = c * 64;
        #pragma unroll
        for (int i = 0; i < 4; i++) {
            const int sg = ls0 + i;
            const uint32_t so = SWZ((uint32_t)(lr * 128 + sg * 16));
            cp16(sb + so, ga.Amh + abase + t0 + sg * 8);
            if (p3) cp16(sb + TILE_B + so, ga.Aml + abase + t0 + sg * 8);
        }
        #pragma unroll
        for (int i = 0; i < 2; i++) {
            const int sg = vs0 + i;
            const uint32_t so = SWZ((uint32_t)(vr * 128 + sg * 16));
            cp16(sb + 2 * TILE_B + so, ga.Vh + vbase + (size_t)t0 * D + sg * 8);
            if (p3)
                cp16(sb + 2 * TILE_B + VT_B + so, ga.Vl + vbase + (size_t)t0 * D + sg * 8);
        }
    };

    float acc[2][4][4];
    #pragma unroll
    for (int mi = 0; mi < 2; mi++)
        #pragma unroll
        for (int ni = 0; ni < 4; ni++)
            #pragma unroll
            for (int q = 0; q < 4; q++) acc[mi][ni][q] = 0.f;

    const int a_r = wm * 32 + (lane & 15);
    const int a_kseg = (lane >> 4);
    const int tg = lane >> 3;
    const int tr = lane & 7;

    load_chunk(0, 0); cp_commit();
    load_chunk(1, 1); cp_commit();

    for (int c = 0; c < 16; c++) {
        if (c < 15) { cp_wait<1>(); } else { cp_wait<0>(); }
        __syncthreads();

        const uint32_t sA  = base + (c & 1) * AV_STAGE;
        const uint32_t sAl = sA + TILE_B;
        const uint32_t sV  = sA + 2 * TILE_B;
        const uint32_t sVl = sV + VT_B;

        #pragma unroll
        for (int ks = 0; ks < 4; ks++) {
            const int k0 = ks * 16;
            uint32_t ah[2][4], al[2][4];
            #pragma unroll
            for (int mi = 0; mi < 2; mi++) {
                const uint32_t ao = SWZ((uint32_t)((a_r + mi * 16) * 128 +
                                                   (k0 + a_kseg * 8) * 2));
                ldsm4(ah[mi][0], ah[mi][1], ah[mi][2], ah[mi][3], sA + ao);
                if (p3) ldsm4(al[mi][0], al[mi][1], al[mi][2], al[mi][3], sAl + ao);
            }
            #pragma unroll
            for (int p = 0; p < 2; p++) {
                const uint32_t bo = SWZ((uint32_t)(
                    (k0 + (tg & 1) * 8 + tr) * 128 +
                    (wn * 32 + p * 16 + (tg >> 1) * 8) * 2));
                uint32_t bh4[4], bl4[4];
                ldsm4t(bh4[0], bh4[1], bh4[2], bh4[3], sV + bo);
                if (p3) ldsm4t(bl4[0], bl4[1], bl4[2], bl4[3], sVl + bo);
                #pragma unroll
                for (int mi = 0; mi < 2; mi++) {
                    #pragma unroll
                    for (int nj = 0; nj < 2; nj++) {
                        float* a4 = acc[mi][p * 2 + nj];
                        mma16816(a4, ah[mi], &bh4[nj * 2]);
                        if (p3) {
                            mma16816(a4, ah[mi], &bl4[nj * 2]);
                            mma16816(a4, al[mi], &bh4[nj * 2]);
                        }
                    }
                }
            }
        }
        __syncthreads();
        if (c + 2 < 16) { load_chunk(c + 2, c & 1); cp_commit(); }
    }

    const int er = lane >> 2;
    const int ec = (lane & 3) * 2;
    #pragma unroll
    for (int mi = 0; mi < 2; mi++) {
        #pragma unroll
        for (int ni = 0; ni < 4; ni++) {
            const int gr = s0 + wm * 32 + mi * 16 + er;
            const int gc = wn * 32 + ni * 8 + ec;
            float v0 = acc[mi][ni][0], v1 = acc[mi][ni][1];
            float v2 = acc[mi][ni][2], v3 = acc[mi][ni][3];
            const size_t idx = (size_t)(b * S + gr) * D + h * 64 + gc;
            if (ga.epi == 1) {
                const float c0 = C0V * ga.cs[b * D + h * 64 + gc];
                const float c1 = C0V * ga.cs[b * D + h * 64 + gc + 1];
                v0 += c0; v1 += c1; v2 += c0; v3 += c1;
                float s;
                s = sqrtf(v0 + EPSV) + EPSV; v0 = s * s;
                s = sqrtf(v1 + EPSV) + EPSV; v1 = s * s;
                s = sqrtf(v2 + EPSV) + EPSV; v2 = s * s;
                s = sqrtf(v3 + EPSV) + EPSV; v3 = s * s;
                store_h2(ga.Yh, idx, v0, v1);
                store_h2(ga.Yh, idx + 8 * (size_t)D, v2, v3);
            } else {
                store_hl2(ga.Yh, ga.Yl, idx, v0, v1);
                store_hl2(ga.Yh, ga.Yl, idx + 8 * (size_t)D, v2, v3);
            }
        }
    }
}

// ---------------------------------------------------------------------------
extern "C" void kernel_launch(void* const* d_in, const int* in_sizes, int n_in,
                              void* d_out, int out_size)
{
    const float* q_loc   = (const float*)d_in[0];
    const float* k_loc   = (const float*)d_in[2];
    const float* v_loc   = (const float*)d_in[4];
    const float* v_scale = (const float*)d_in[5];
    const float* Wq = (const float*)d_in[6];
    const float* bq = (const float*)d_in[7];
    const float* Wk = (const float*)d_in[8];
    const float* bk = (const float*)d_in[9];
    const float* Wv = (const float*)d_in[10];
    const float* bv = (const float*)d_in[11];
    const float* Wo = (const float*)d_in[12];
    const float* bo = (const float*)d_in[13];
    const float* tau = (const float*)d_in[14];

    float* out_loc   = (float*)d_out;
    float* out_scale = (float*)d_out + PROJ;

    float *lg, *cs;
    cudaGetSymbolAddress((void**)&lg, g_logits);
    cudaGetSymbolAddress((void**)&cs, g_colsum);
    bf16 *amuh, *amul, *avarw;
    cudaGetSymbolAddress((void**)&amuh, g_amuh); cudaGetSymbolAddress((void**)&amul, g_amul);
    cudaGetSymbolAddress((void**)&avarw, g_avarw);
    bf16 *qh,*ql,*kh,*kl,*vh,*vl,*vsh;
    cudaGetSymbolAddress((void**)&qh, g_qh);   cudaGetSymbolAddress((void**)&ql, g_ql);
    cudaGetSymbolAddress((void**)&kh, g_kh);   cudaGetSymbolAddress((void**)&kl, g_kl);
    cudaGetSymbolAddress((void**)&vh, g_vh);   cudaGetSymbolAddress((void**)&vl, g_vl);
    cudaGetSymbolAddress((void**)&vsh, g_vsh);
    bf16 *qmh,*qml,*kmh,*kml,*vmh,*vml,*vvh,*ymh,*yml,*pph;
    cudaGetSymbolAddress((void**)&qmh, g_qmh); cudaGetSymbolAddress((void**)&qml, g_qml);
    cudaGetSymbolAddress((void**)&kmh, g_kmh); cudaGetSymbolAddress((void**)&kml, g_kml);
    cudaGetSymbolAddress((void**)&vmh, g_vmh); cudaGetSymbolAddress((void**)&vml, g_vml);
    cudaGetSymbolAddress((void**)&vvh, g_vvh);
    cudaGetSymbolAddress((void**)&ymh, g_ymh); cudaGetSymbolAddress((void**)&yml, g_yml);
    cudaGetSymbolAddress((void**)&pph, g_pph);
    bf16 *wqh,*wql,*wkh,*wkl,*wvh,*wvl,*wvsh,*woh,*wol,*wosh;
    cudaGetSymbolAddress((void**)&wqh, g_wqh);   cudaGetSymbolAddress((void**)&wql, g_wql);
    cudaGetSymbolAddress((void**)&wkh, g_wkh);   cudaGetSymbolAddress((void**)&wkl, g_wkl);
    cudaGetSymbolAddress((void**)&wvh, g_wvh);   cudaGetSymbolAddress((void**)&wvl, g_wvl);
    cudaGetSymbolAddress((void**)&wvsh, g_wvsh);
    cudaGetSymbolAddress((void**)&woh, g_woh);   cudaGetSymbolAddress((void**)&wol, g_wol);
    cudaGetSymbolAddress((void**)&wosh, g_wosh);

    cudaFuncSetAttribute(gemm_mma_b, cudaFuncAttributeMaxDynamicSharedMemorySize, GSMEM);
    cudaFuncSetAttribute(qk_hmma,    cudaFuncAttributeMaxDynamicSharedMemorySize, QK_SMEM);
    cudaFuncSetAttribute(av_hmma_b,  cudaFuncAttributeMaxDynamicSharedMemorySize, AV_SMEM);

    // hi/lo conversion
    CvtParams P;
    const int PN = (int)PROJ, WN = (int)WSZ;
    P.src[0] = q_loc;   P.hi[0] = qh;   P.lo[0] = ql;      P.n[0] = PN; P.sq[0] = 0;
    P.src[1] = k_loc;   P.hi[1] = kh;   P.lo[1] = kl;      P.n[1] = PN; P.sq[1] = 0;
    P.src[2] = v_loc;   P.hi[2] = vh;   P.lo[2] = vl;      P.n[2] = PN; P.sq[2] = 0;
    P.src[3] = v_scale; P.hi[3] = vsh;  P.lo[3] = nullptr; P.n[3] = PN; P.sq[3] = 1;
    P.src[4] = Wq;      P.hi[4] = wqh;  P.lo[4] = wql;     P.n[4] = WN; P.sq[4] = 0;
    P.src[5] = Wk;      P.hi[5] = wkh;  P.lo[5] = wkl;     P.n[5] = WN; P.sq[5] = 0;
    P.src[6] = Wv;      P.hi[6] = wvh;  P.lo[6] = wvl;     P.n[6] = WN; P.sq[6] = 0;
    P.src[7] = Wv;      P.hi[7] = wvsh; P.lo[7] = nullptr; P.n[7] = WN; P.sq[7] = 1;
    P.src[8] = Wo;      P.hi[8] = woh;  P.lo[8] = wol;     P.n[8] = WN; P.sq[8] = 0;
    P.src[9] = Wo;      P.hi[9] = wosh; P.lo[9] = nullptr; P.n[9] = WN; P.sq[9] = 1;
    P.cs = cs;
    convert_all<<<dim3(PN / 1024, 10), 256>>>(P);

    // batched projections
    GemmBatch bp;
    bp.a[0] = { qh,  ql,      wqh,  wql,    bq,      nullptr, qmh, qml,     3, 3 };
    bp.a[1] = { kh,  kl,      wkh,  wkl,    bk,      nullptr, kmh, kml,     3, 3 };
    bp.a[2] = { vh,  vl,      wvh,  wvl,    bv,      nullptr, vmh, vml,     3, 3 };
    bp.a[3] = { vsh, nullptr, wvsh, nullptr,nullptr, nullptr, vvh, nullptr, 5, 1 };
    gemm_mma_b<<<dim3(GN / 128, BS / 128, 4), 256, GSMEM>>>(bp);

    // colsum over t of vvar
    colsum_kernel<<<dim3(B * D / 256, S / 64), 256>>>(cs, vvh);

    // attention
    qk_hmma<<<dim3(S / 128, S / 128, B * H), 256, QK_SMEM>>>(lg, qmh, qml, kmh, kml, tau);
    softmax_kernel<<<B * H * S, 256>>>(amuh, amul, avarw, lg, tau);

    // batched AV: z=0 mean (3-pass), z=1 variance (1-pass + colsum)
    AvBatch av;
    av.a[0] = { ymh, yml,     amuh,  amul,    vmh, vml,     nullptr, 0 };
    av.a[1] = { pph, nullptr, avarw, nullptr, vvh, nullptr, cs,      1 };
    av_hmma_b<<<dim3(S / 128, B * H, 2), 256, AV_SMEM>>>(av);

    // batched output projections
    GemmBatch bo2;
    bo2.a[0] = { ymh, yml,     woh,  wol,    bo,      out_loc,   nullptr, nullptr, 0, 3 };
    bo2.a[1] = { pph, nullptr, wosh, nullptr,nullptr, out_scale, nullptr, nullptr, 2, 1 };
    bo2.a[2] = bo2.a[0];
    bo2.a[3] = bo2.a[0];
    gemm_mma_b<<<dim3(GN / 128, BS / 128, 2), 256, GSMEM>>>(bo2);
}

// round 10
// speedup vs baseline: 1.1768x; 1.0956x over previous
#include <cuda_runtime.h>
#include <cuda_bf16.h>
#include <math.h>
#include <stdint.h>

#define EPSV 1e-6f
using bf16 = __nv_bfloat16;

constexpr int B = 2, S = 1024, D = 1024, H = 16, HD = 64;
constexpr int BS = B * S;                         // 2048
constexpr size_t PROJ = (size_t)BS * D;           // 2M
constexpr size_t ATTN = (size_t)B * H * S * S;    // 32M
constexpr size_t WSZ  = (size_t)D * D;            // 1M
#define C0V (1e-4f + EPSV)

// ---------------- scratch ---------------------------------------------------
__device__ float g_logits[ATTN];
__device__ float g_colsum[B * D];
__device__ bf16 g_amuh[ATTN], g_amul[ATTN], g_avarw[ATTN];
__device__ bf16 g_qh[PROJ], g_ql[PROJ], g_kh[PROJ], g_kl[PROJ];
__device__ bf16 g_vh[PROJ], g_vl[PROJ], g_vsh[PROJ];
__device__ bf16 g_qmh[PROJ], g_qml[PROJ], g_kmh[PROJ], g_kml[PROJ];
__device__ bf16 g_vmh[PROJ], g_vml[PROJ], g_vvh[PROJ];
__device__ bf16 g_ymh[PROJ], g_yml[PROJ], g_pph[PROJ];
__device__ bf16 g_wqh[WSZ], g_wql[WSZ], g_wkh[WSZ], g_wkl[WSZ];
__device__ bf16 g_wvh[WSZ], g_wvl[WSZ], g_wvsh[WSZ];
__device__ bf16 g_woh[WSZ], g_wol[WSZ], g_wosh[WSZ];

// ---------------- helpers ---------------------------------------------------
__device__ __forceinline__ uint32_t smem_u32(const void* p) {
    uint32_t a;
    asm("{ .reg .u64 t; cvta.to.shared.u64 t, %1; cvt.u32.u64 %0, t; }" : "=r"(a) : "l"(p));
    return a;
}
#define SWZ(o) ((o) ^ (((o) >> 3) & 0x70))

__device__ __forceinline__ void cp16(uint32_t dst, const void* src) {
    asm volatile("cp.async.cg.shared.global [%0], [%1], 16;" :: "r"(dst), "l"(src));
}
__device__ __forceinline__ void cp_commit() {
    asm volatile("cp.async.commit_group;" ::: "memory");
}
template<int N>
__device__ __forceinline__ void cp_wait() {
    asm volatile("cp.async.wait_group %0;" :: "n"(N) : "memory");
}
__device__ __forceinline__ void ldsm4(uint32_t& r0, uint32_t& r1, uint32_t& r2, uint32_t& r3,
                                      uint32_t addr) {
    asm volatile("ldmatrix.sync.aligned.m8n8.x4.shared.b16 {%0,%1,%2,%3}, [%4];"
                 : "=r"(r0), "=r"(r1), "=r"(r2), "=r"(r3) : "r"(addr));
}
__device__ __forceinline__ void ldsm4t(uint32_t& r0, uint32_t& r1, uint32_t& r2, uint32_t& r3,
                                       uint32_t addr) {
    asm volatile("ldmatrix.sync.aligned.m8n8.x4.trans.shared.b16 {%0,%1,%2,%3}, [%4];"
                 : "=r"(r0), "=r"(r1), "=r"(r2), "=r"(r3) : "r"(addr));
}
__device__ __forceinline__ void mma16816(float* d, const uint32_t* a, const uint32_t* b) {
    asm volatile(
        "mma.sync.aligned.m16n8k16.row.col.f32.bf16.bf16.f32 "
        "{%0,%1,%2,%3}, {%4,%5,%6,%7}, {%8,%9}, {%0,%1,%2,%3};"
        : "+f"(d[0]), "+f"(d[1]), "+f"(d[2]), "+f"(d[3])
        : "r"(a[0]), "r"(a[1]), "r"(a[2]), "r"(a[3]), "r"(b[0]), "r"(b[1]));
}
__device__ __forceinline__ void split2(float v, bf16& h, bf16& l) {
    h = __float2bfloat16(v);
    l = __float2bfloat16(v - __bfloat162float(h));
}
__device__ __forceinline__ void store_hl2(bf16* Ph, bf16* Pl, size_t idx, float v0, float v1) {
    bf16 h0, l0, h1, l1;
    split2(v0, h0, l0); split2(v1, h1, l1);
    __nv_bfloat162 ph; ph.x = h0; ph.y = h1;
    __nv_bfloat162 pl; pl.x = l0; pl.y = l1;
    *(__nv_bfloat162*)(Ph + idx) = ph;
    *(__nv_bfloat162*)(Pl + idx) = pl;
}
__device__ __forceinline__ void store_h2(bf16* Ph, size_t idx, float v0, float v1) {
    __nv_bfloat162 ph;
    ph.x = __float2bfloat16(v0); ph.y = __float2bfloat16(v1);
    *(__nv_bfloat162*)(Ph + idx) = ph;
}

// ---------------------------------------------------------------------------
// convert_all
// ---------------------------------------------------------------------------
struct CvtParams {
    const float* src[10];
    bf16* hi[10];
    bf16* lo[10];
    int n[10];
    int sq[10];
    float* cs;
};

__global__ void __launch_bounds__(256) convert_all(CvtParams P) {
    if (blockIdx.y == 0 && blockIdx.x == 0) {
        for (int i = threadIdx.x; i < B * D; i += 256) P.cs[i] = 0.f;
    }
    const int r = blockIdx.y;
    const int i4 = (blockIdx.x * 256 + threadIdx.x) * 4;
    if (i4 >= P.n[r]) return;
    float4 v = *(const float4*)(P.src[r] + i4);
    if (P.sq[r]) { v.x *= v.x; v.y *= v.y; v.z *= v.z; v.w *= v.w; }
    if (P.lo[r]) {
        store_hl2(P.hi[r], P.lo[r], i4, v.x, v.y);
        store_hl2(P.hi[r], P.lo[r], i4 + 2, v.z, v.w);
    } else {
        store_h2(P.hi[r], i4, v.x, v.y);
        store_h2(P.hi[r], i4 + 2, v.z, v.w);
    }
}

// ---------------------------------------------------------------------------
// colsum
// ---------------------------------------------------------------------------
__global__ void __launch_bounds__(256) colsum_kernel(float* cs, const bf16* vv) {
    const int d = blockIdx.x * 256 + threadIdx.x;
    const int b = d >> 10, dd = d & 1023;
    const int t0 = blockIdx.y * 64;
    const bf16* p = vv + (size_t)b * S * D + (size_t)t0 * D + dd;
    float s = 0.f;
    #pragma unroll 8
    for (int t = 0; t < 64; t++) s += __bfloat162float(p[(size_t)t * D]);
    atomicAdd(cs + d, s);
}

// ---------------------------------------------------------------------------
// Batched projection-shaped GEMM: 512 threads, 16 warps (4x4), 32x32/warp.
// 128x128 CTA tile, BK=64, 3-stage cp.async pipeline.
// epi: 0 fp32+bias; 2 fp32 sqrt; 3 bf16 hi/lo +bias; 5 bf16 single (sqrt+eps)^2
// ---------------------------------------------------------------------------
constexpr int GK = 1024;
constexpr int GN = 1024;
constexpr uint32_t TILE_B  = 16384;
constexpr uint32_t STAGE_B = 4 * TILE_B;
constexpr uint32_t GSMEM   = 3 * STAGE_B + 1024;

struct GemmArgs {
    const bf16 *Ah, *Al, *Bh, *Bl;
    const float* bias;
    float* Cf;
    bf16 *Ch, *Cl;
    int epi;
    int passes;
};
struct GemmBatch { GemmArgs a[4]; };

__global__ void __launch_bounds__(512, 1) gemm_mma_b(GemmBatch bat)
{
    extern __shared__ char dsraw[];
    char* dsm = (char*)(((uintptr_t)dsraw + 1023) & ~(uintptr_t)1023);
    const uint32_t base = smem_u32(dsm);

    const GemmArgs ga = bat.a[blockIdx.z];
    const bool p3 = (ga.passes == 3);

    const int tid  = threadIdx.x;
    const int wid  = tid >> 5;
    const int lane = tid & 31;
    const int wm = wid & 3;          // rows wm*32
    const int wn = wid >> 2;         // cols wn*32  (0..3)
    const int row0 = blockIdx.y * 128;
    const int col0 = blockIdx.x * 128;

    // loaders: 4 threads/row, 2 x 16B segments each
    const int lr = tid >> 2;                  // 0..127
    const int ls0 = (tid & 3) * 2;            // 0,2,4,6
    const size_t aoff = (size_t)(row0 + lr) * GK;
    const size_t boff = (size_t)(col0 + lr) * GK;

    auto load_chunk = [&](int c, int st) {
        const uint32_t sb = base + st * STAGE_B;
        const int k0 = c * 64;
        #pragma unroll
        for (int i = 0; i < 2; i++) {
            const int sg = ls0 + i;
            const uint32_t so = SWZ((uint32_t)(lr * 128 + sg * 16));
            const size_t gai = aoff + k0 + sg * 8;
            const size_t gbi = boff + k0 + sg * 8;
            cp16(sb + so,              ga.Ah + gai);
            cp16(sb + 2 * TILE_B + so, ga.Bh + gbi);
            if (p3) {
                cp16(sb + TILE_B + so,     ga.Al + gai);
                cp16(sb + 3 * TILE_B + so, ga.Bl + gbi);
            }
        }
    };

    float acc[2][4][4];
    #pragma unroll
    for (int mi = 0; mi < 2; mi++)
        #pragma unroll
        for (int ni = 0; ni < 4; ni++)
            #pragma unroll
            for (int q = 0; q < 4; q++) acc[mi][ni][q] = 0.f;

    const int a_r = wm * 32 + (lane & 15);
    const int a_kseg = (lane >> 4);
    const int b_r = wn * 32 + ((lane >> 4) & 1) * 8 + (lane & 7);
    const int b_kseg = (lane >> 3) & 1;

    load_chunk(0, 0); cp_commit();
    load_chunk(1, 1); cp_commit();

    for (int c = 0; c < 16; c++) {
        if (c + 2 < 16) load_chunk(c + 2, (c + 2) % 3);
        cp_commit();
        cp_wait<2>();
        __syncthreads();

        const uint32_t sA = base + (c % 3) * STAGE_B;
        const uint32_t sB = sA + 2 * TILE_B;

        #pragma unroll
        for (int ks = 0; ks < 4; ks++) {
            const int k0 = ks * 16;
            uint32_t ah[2][4], al[2][4];
            #pragma unroll
            for (int mi = 0; mi < 2; mi++) {
                const uint32_t ao = SWZ((uint32_t)((a_r + mi * 16) * 128 +
                                                   (k0 + a_kseg * 8) * 2));
                ldsm4(ah[mi][0], ah[mi][1], ah[mi][2], ah[mi][3], sA + ao);
                if (p3) ldsm4(al[mi][0], al[mi][1], al[mi][2], al[mi][3], sA + TILE_B + ao);
            }
            #pragma unroll
            for (int p = 0; p < 2; p++) {
                const uint32_t bo = SWZ((uint32_t)((b_r + p * 16) * 128 +
                                                   (k0 + b_kseg * 8) * 2));
                uint32_t bh4[4], bl4[4];
                ldsm4(bh4[0], bh4[1], bh4[2], bh4[3], sB + bo);
                if (p3) ldsm4(bl4[0], bl4[1], bl4[2], bl4[3], sB + TILE_B + bo);
                #pragma unroll
                for (int mi = 0; mi < 2; mi++) {
                    #pragma unroll
                    for (int nj = 0; nj < 2; nj++) {
                        float* a4 = acc[mi][p * 2 + nj];
                        mma16816(a4, ah[mi], &bh4[nj * 2]);
                        if (p3) {
                            mma16816(a4, ah[mi], &bl4[nj * 2]);
                            mma16816(a4, al[mi], &bh4[nj * 2]);
                        }
                    }
                }
            }
        }
        __syncthreads();
    }

    const int er = lane >> 2;
    const int ec = (lane & 3) * 2;
    const int epi = ga.epi;

    if (epi <= 2) {
        #pragma unroll
        for (int mi = 0; mi < 2; mi++) {
            #pragma unroll
            for (int ni = 0; ni < 4; ni++) {
                const int gr = row0 + wm * 32 + mi * 16 + er;
                const int gc = col0 + wn * 32 + ni * 8 + ec;
                float v0 = acc[mi][ni][0], v1 = acc[mi][ni][1];
                float v2 = acc[mi][ni][2], v3 = acc[mi][ni][3];
                if (epi == 0) {
                    const float b0 = ga.bias[gc], b1 = ga.bias[gc + 1];
                    v0 += b0; v1 += b1; v2 += b0; v3 += b1;
                } else {
                    v0 = sqrtf(v0); v1 = sqrtf(v1); v2 = sqrtf(v2); v3 = sqrtf(v3);
                }
                float2 w0 = {v0, v1}, w1 = {v2, v3};
                *(float2*)(ga.Cf + (size_t)gr * GN + gc)       = w0;
                *(float2*)(ga.Cf + (size_t)(gr + 8) * GN + gc) = w1;
            }
        }
    } else if (epi == 3) {
        bf16* Hs = (bf16*)dsm;
        bf16* Ls = (bf16*)(dsm + 32768);
        #pragma unroll
        for (int mi = 0; mi < 2; mi++) {
            #pragma unroll
            for (int ni = 0; ni < 4; ni++) {
                const int rl = wm * 32 + mi * 16 + er;
                const int cl = wn * 32 + ni * 8 + ec;
                float v0 = acc[mi][ni][0], v1 = acc[mi][ni][1];
                float v2 = acc[mi][ni][2], v3 = acc[mi][ni][3];
                const float b0 = ga.bias[col0 + cl], b1 = ga.bias[col0 + cl + 1];
                v0 += b0; v1 += b1; v2 += b0; v3 += b1;
                bf16 h0, l0, h1, l1;
                split2(v0, h0, l0); split2(v1, h1, l1);
                __nv_bfloat162 ph; ph.x = h0; ph.y = h1;
                __nv_bfloat162 pl; pl.x = l0; pl.y = l1;
                *(__nv_bfloat162*)(Hs + rl * 128 + cl) = ph;
                *(__nv_bfloat162*)(Ls + rl * 128 + cl) = pl;
                split2(v2, h0, l0); split2(v3, h1, l1);
                ph.x = h0; ph.y = h1; pl.x = l0; pl.y = l1;
                *(__nv_bfloat162*)(Hs + (rl + 8) * 128 + cl) = ph;
                *(__nv_bfloat162*)(Ls + (rl + 8) * 128 + cl) = pl;
            }
        }
        __syncthreads();
        #pragma unroll
        for (int i = 0; i < 4; i++) {
            const int idx = i * 512 + tid;     // 0..2047
            const int r = idx >> 4;
            const int sg = idx & 15;
            const size_t gp = (size_t)(row0 + r) * GN + col0 + sg * 8;
            *(uint4*)(ga.Ch + gp) = *(const uint4*)((const char*)Hs + r * 256 + sg * 16);
            *(uint4*)(ga.Cl + gp) = *(const uint4*)((const char*)Ls + r * 256 + sg * 16);
        }
    } else {   // epi == 5
        bf16* Hs = (bf16*)dsm;
        #pragma unroll
        for (int mi = 0; mi < 2; mi++) {
            #pragma unroll
            for (int ni = 0; ni < 4; ni++) {
                const int rl = wm * 32 + mi * 16 + er;
                const int cl = wn * 32 + ni * 8 + ec;
                float v0 = acc[mi][ni][0], v1 = acc[mi][ni][1];
                float v2 = acc[mi][ni][2], v3 = acc[mi][ni][3];
                float s;
                s = sqrtf(v0) + EPSV; v0 = s * s;
                s = sqrtf(v1) + EPSV; v1 = s * s;
                s = sqrtf(v2) + EPSV; v2 = s * s;
                s = sqrtf(v3) + EPSV; v3 = s * s;
                __nv_bfloat162 ph;
                ph.x = __float2bfloat16(v0); ph.y = __float2bfloat16(v1);
                *(__nv_bfloat162*)(Hs + rl * 128 + cl) = ph;
                ph.x = __float2bfloat16(v2); ph.y = __float2bfloat16(v3);
                *(__nv_bfloat162*)(Hs + (rl + 8) * 128 + cl) = ph;
            }
        }
        __syncthreads();
        #pragma unroll
        for (int i = 0; i < 4; i++) {
            const int idx = i * 512 + tid;
            const int r = idx >> 4;
            const int sg = idx & 15;
            const size_t gp = (size_t)(row0 + r) * GN + col0 + sg * 8;
            *(uint4*)(ga.Ch + gp) = *(const uint4*)((const char*)Hs + r * 256 + sg * 16);
        }
    }
}

// ---------------------------------------------------------------------------
// qk_hmma (unchanged from R9)
// ---------------------------------------------------------------------------
constexpr uint32_t QK_SMEM = 4 * TILE_B + 1024;

__global__ void __launch_bounds__(256, 2) qk_hmma(
    float* __restrict__ L,
    const bf16* __restrict__ Qh_, const bf16* __restrict__ Ql_,
    const bf16* __restrict__ Kh_, const bf16* __restrict__ Kl_,
    const float* __restrict__ tau)
{
    extern __shared__ char dsraw[];
    char* dsm = (char*)(((uintptr_t)dsraw + 1023) & ~(uintptr_t)1023);
    const uint32_t base = smem_u32(dsm);

    const int tid = threadIdx.x;
    const int wid = tid >> 5;
    const int lane = tid & 31;
    const int wm = wid & 3, wn = wid >> 2;
    const int bh = blockIdx.z;
    const int b = bh >> 4, h = bh & 15;
    const int s0 = blockIdx.y * 128, t0 = blockIdx.x * 128;

    const int lr = tid >> 1;
    const int ls0 = (tid & 1) * 4;
    const size_t qoff = (size_t)(b * S + s0 + lr) * D + h * 64;
    const size_t koff = (size_t)(b * S + t0 + lr) * D + h * 64;
    #pragma unroll
    for (int i = 0; i < 4; i++) {
        const int sg = ls0 + i;
        const uint32_t so = SWZ((uint32_t)(lr * 128 + sg * 16));
        cp16(base + so,              Qh_ + qoff + sg * 8);
        cp16(base + TILE_B + so,     Ql_ + qoff + sg * 8);
        cp16(base + 2 * TILE_B + so, Kh_ + koff + sg * 8);
        cp16(base + 3 * TILE_B + so, Kl_ + koff + sg * 8);
    }
    cp_commit();
    cp_wait<0>();
    __syncthreads();

    float acc[2][8][4];
    #pragma unroll
    for (int mi = 0; mi < 2; mi++)
        #pragma unroll
        for (int ni = 0; ni < 8; ni++)
            #pragma unroll
            for (int q = 0; q < 4; q++) acc[mi][ni][q] = 0.f;

    const int a_r = wm * 32 + (lane & 15);
    const int a_kseg = (lane >> 4);
    const int b_r = wn * 64 + ((lane >> 4) & 1) * 8 + (lane & 7);
    const int b_kseg = (lane >> 3) & 1;
    const uint32_t sA = base, sAl = base + TILE_B;
    const uint32_t sB = base + 2 * TILE_B, sBl = base + 3 * TILE_B;

    #pragma unroll
    for (int ks = 0; ks < 4; ks++) {
        const int k0 = ks * 16;
        uint32_t ah[2][4], al[2][4];
        #pragma unroll
        for (int mi = 0; mi < 2; mi++) {
            const uint32_t ao = SWZ((uint32_t)((a_r + mi * 16) * 128 + (k0 + a_kseg * 8) * 2));
            ldsm4(ah[mi][0], ah[mi][1], ah[mi][2], ah[mi][3], sA + ao);
            ldsm4(al[mi][0], al[mi][1], al[mi][2], al[mi][3], sAl + ao);
        }
        #pragma unroll
        for (int p = 0; p < 4; p++) {
            const uint32_t bo = SWZ((uint32_t)((b_r + p * 16) * 128 + (k0 + b_kseg * 8) * 2));
            uint32_t bh4[4], bl4[4];
            ldsm4(bh4[0], bh4[1], bh4[2], bh4[3], sB + bo);
            ldsm4(bl4[0], bl4[1], bl4[2], bl4[3], sBl + bo);
            #pragma unroll
            for (int mi = 0; mi < 2; mi++) {
                #pragma unroll
                for (int nj = 0; nj < 2; nj++) {
                    float* a4 = acc[mi][p * 2 + nj];
                    mma16816(a4, ah[mi], &bh4[nj * 2]);
                    mma16816(a4, ah[mi], &bl4[nj * 2]);
                    mma16816(a4, al[mi], &bh4[nj * 2]);
                }
            }
        }
    }

    const float scale = 1.f / (8.f * tau[0]);
    const int er = lane >> 2;
    const int ec = (lane & 3) * 2;
    float* Lb = L + (size_t)bh * S * S;
    #pragma unroll
    for (int mi = 0; mi < 2; mi++) {
        #pragma unroll
        for (int ni = 0; ni < 8; ni++) {
            const int gr = s0 + wm * 32 + mi * 16 + er;
            const int gc = t0 + wn * 64 + ni * 8 + ec;
            float2 w0 = {acc[mi][ni][0] * scale, acc[mi][ni][1] * scale};
            float2 w1 = {acc[mi][ni][2] * scale, acc[mi][ni][3] * scale};
            *(float2*)(Lb + (size_t)gr * S + gc)       = w0;
            *(float2*)(Lb + (size_t)(gr + 8) * S + gc) = w1;
        }
    }
}

// ---------------------------------------------------------------------------
// softmax (R9 + __expf)
// ---------------------------------------------------------------------------
__global__ void __launch_bounds__(256) softmax_kernel(
    bf16* __restrict__ amuh, bf16* __restrict__ amul, bf16* __restrict__ avarw,
    const float* __restrict__ logits, const float* __restrict__ tau)
{
    __shared__ float shm[8], sh1[8], sh2[8];
    const int tid = threadIdx.x;
    const size_t row = blockIdx.x;
    const float4 v = ((const float4*)(logits + row * (size_t)S))[tid];

    float m = fmaxf(fmaxf(v.x, v.y), fmaxf(v.z, v.w));
    #pragma unroll
    for (int o = 16; o; o >>= 1) m = fmaxf(m, __shfl_xor_sync(0xffffffffu, m, o));
    if ((tid & 31) == 0) shm[tid >> 5] = m;
    __syncthreads();
    m = shm[tid & 7];
    #pragma unroll
    for (int o = 4; o; o >>= 1) m = fmaxf(m, __shfl_xor_sync(0xffffffffu, m, o));

    const float tv = tau[0];
    const float l_var = ((0.1f + EPSV) / 64.f + EPSV) / (tv * tv) + EPSV;
    const float invc = rsqrtf(1.f + 0.39269908169872414f * l_var);

    float4 e1, e2;
    e1.x = __expf(v.x - m); e1.y = __expf(v.y - m);
    e1.z = __expf(v.z - m); e1.w = __expf(v.w - m);
    e2.x = __expf((v.x - m) * invc); e2.y = __expf((v.y - m) * invc);
    e2.z = __expf((v.z - m) * invc); e2.w = __expf((v.w - m) * invc);

    float s1 = e1.x + e1.y + e1.z + e1.w;
    float s2 = e2.x + e2.y + e2.z + e2.w;
    #pragma unroll
    for (int o = 16; o; o >>= 1) {
        s1 += __shfl_xor_sync(0xffffffffu, s1, o);
        s2 += __shfl_xor_sync(0xffffffffu, s2, o);
    }
    if ((tid & 31) == 0) { sh1[tid >> 5] = s1; sh2[tid >> 5] = s2; }
    __syncthreads();
    s1 = sh1[tid & 7]; s2 = sh2[tid & 7];
    #pragma unroll
    for (int o = 4; o; o >>= 1) {
        s1 += __shfl_xor_sync(0xffffffffu, s1, o);
        s2 += __shfl_xor_sync(0xffffffffu, s2, o);
    }

    const float r1 = 1.f / s1, r2 = 1.f / s2;
    float mu[4], w[4];
    {
        float t, r;
        t = e1.x * r1; r = e2.x * r2; mu[0] = t + r; w[0] = r * (1.f - r) * l_var;
        t = e1.y * r1; r = e2.y * r2; mu[1] = t + r; w[1] = r * (1.f - r) * l_var;
        t = e1.z * r1; r = e2.z * r2; mu[2] = t + r; w[2] = r * (1.f - r) * l_var;
        t = e1.w * r1; r = e2.w * r2; mu[3] = t + r; w[3] = r * (1.f - r) * l_var;
    }
    const size_t o0 = row * (size_t)S + tid * 4;
    store_hl2(amuh, amul, o0,     mu[0], mu[1]);
    store_hl2(amuh, amul, o0 + 2, mu[2], mu[3]);
    store_h2(avarw, o0,     w[0], w[1]);
    store_h2(avarw, o0 + 2, w[2], w[3]);
}

// ---------------------------------------------------------------------------
// av_hmma_b (unchanged from R9)
// ---------------------------------------------------------------------------
constexpr uint32_t VT_B     = 8192;
constexpr uint32_t AV_STAGE = 2 * TILE_B + 2 * VT_B;
constexpr uint32_t AV_SMEM  = 2 * AV_STAGE + 1024;

struct AvArgs {
    bf16 *Yh, *Yl;
    const bf16 *Amh, *Aml, *Vh, *Vl;
    const float* cs;
    int epi;
};
struct AvBatch { AvArgs a[2]; };

__global__ void __launch_bounds__(256, 2) av_hmma_b(AvBatch bat)
{
    extern __shared__ char dsraw[];
    char* dsm = (char*)(((uintptr_t)dsraw + 1023) & ~(uintptr_t)1023);
    const uint32_t base = smem_u32(dsm);

    const AvArgs ga = bat.a[blockIdx.z];
    const bool p3 = (ga.epi == 0);

    const int tid = threadIdx.x;
    const int wid = tid >> 5;
    const int lane = tid & 31;
    const int wm = wid & 3, wn = wid >> 2;
    const int bh = blockIdx.y;
    const int b = bh >> 4, h = bh & 15;
    const int s0 = blockIdx.x * 128;

    const int lr = tid >> 1;
    const int ls0 = (tid & 1) * 4;
    const int vr = tid >> 2;
    const int vs0 = (tid & 3) * 2;
    const size_t abase = ((size_t)bh * S + s0 + lr) * S;
    const size_t vbase = (size_t)b * S * D + h * 64 + (size_t)vr * D;

    auto load_chunk = [&](int c, int st) {
        const uint32_t sb = base + st * AV_STAGE;
        const int t0 = c * 64;
        #pragma unroll
        for (int i = 0; i < 4; i++) {
            const int sg = ls0 + i;
            const uint32_t so = SWZ((uint32_t)(lr * 128 + sg * 16));
            cp16(sb + so, ga.Amh + abase + t0 + sg * 8);
            if (p3) cp16(sb + TILE_B + so, ga.Aml + abase + t0 + sg * 8);
        }
        #pragma unroll
        for (int i = 0; i < 2; i++) {
            const int sg = vs0 + i;
            const uint32_t so = SWZ((uint32_t)(vr * 128 + sg * 16));
            cp16(sb + 2 * TILE_B + so, ga.Vh + vbase + (size_t)t0 * D + sg * 8);
            if (p3)
                cp16(sb + 2 * TILE_B + VT_B + so, ga.Vl + vbase + (size_t)t0 * D + sg * 8);
        }
    };

    float acc[2][4][4];
    #pragma unroll
    for (int mi = 0; mi < 2; mi++)
        #pragma unroll
        for (int ni = 0; ni < 4; ni++)
            #pragma unroll
            for (int q = 0; q < 4; q++) acc[mi][ni][q] = 0.f;

    const int a_r = wm * 32 + (lane & 15);
    const int a_kseg = (lane >> 4);
    const int tg = lane >> 3;
    const int tr = lane & 7;

    load_chunk(0, 0); cp_commit();
    load_chunk(1, 1); cp_commit();

    for (int c = 0; c < 16; c++) {
        if (c < 15) { cp_wait<1>(); } else { cp_wait<0>(); }
        __syncthreads();

        const uint32_t sA  = base + (c & 1) * AV_STAGE;
        const uint32_t sAl = sA + TILE_B;
        const uint32_t sV  = sA + 2 * TILE_B;
        const uint32_t sVl = sV + VT_B;

        #pragma unroll
        for (int ks = 0; ks < 4; ks++) {
            const int k0 = ks * 16;
            uint32_t ah[2][4], al[2][4];
            #pragma unroll
            for (int mi = 0; mi < 2; mi++) {
                const uint32_t ao = SWZ((uint32_t)((a_r + mi * 16) * 128 +
                                                   (k0 + a_kseg * 8) * 2));
                ldsm4(ah[mi][0], ah[mi][1], ah[mi][2], ah[mi][3], sA + ao);
                if (p3) ldsm4(al[mi][0], al[mi][1], al[mi][2], al[mi][3], sAl + ao);
            }
            #pragma unroll
            for (int p = 0; p < 2; p++) {
                const uint32_t bo = SWZ((uint32_t)(
                    (k0 + (tg & 1) * 8 + tr) * 128 +
                    (wn * 32 + p * 16 + (tg >> 1) * 8) * 2));
                uint32_t bh4[4], bl4[4];
                ldsm4t(bh4[0], bh4[1], bh4[2], bh4[3], sV + bo);
                if (p3) ldsm4t(bl4[0], bl4[1], bl4[2], bl4[3], sVl + bo);
                #pragma unroll
                for (int mi = 0; mi < 2; mi++) {
                    #pragma unroll
                    for (int nj = 0; nj < 2; nj++) {
                        float* a4 = acc[mi][p * 2 + nj];
                        mma16816(a4, ah[mi], &bh4[nj * 2]);
                        if (p3) {
                            mma16816(a4, ah[mi], &bl4[nj * 2]);
                            mma16816(a4, al[mi], &bh4[nj * 2]);
                        }
                    }
                }
            }
        }
        __syncthreads();
        if (c + 2 < 16) { load_chunk(c + 2, c & 1); cp_commit(); }
    }

    const int er = lane >> 2;
    const int ec = (lane & 3) * 2;
    #pragma unroll
    for (int mi = 0; mi < 2; mi++) {
        #pragma unroll
        for (int ni = 0; ni < 4; ni++) {
            const int gr = s0 + wm * 32 + mi * 16 + er;
            const int gc = wn * 32 + ni * 8 + ec;
            float v0 = acc[mi][ni][0], v1 = acc[mi][ni][1];
            float v2 = acc[mi][ni][2], v3 = acc[mi][ni][3];
            const size_t idx = (size_t)(b * S + gr) * D + h * 64 + gc;
            if (ga.epi == 1) {
                const float c0 = C0V * ga.cs[b * D + h * 64 + gc];
                const float c1 = C0V * ga.cs[b * D + h * 64 + gc + 1];
                v0 += c0; v1 += c1; v2 += c0; v3 += c1;
                float s;
                s = sqrtf(v0 + EPSV) + EPSV; v0 = s * s;
                s = sqrtf(v1 + EPSV) + EPSV; v1 = s * s;
                s = sqrtf(v2 + EPSV) + EPSV; v2 = s * s;
                s = sqrtf(v3 + EPSV) + EPSV; v3 = s * s;
                store_h2(ga.Yh, idx, v0, v1);
                store_h2(ga.Yh, idx + 8 * (size_t)D, v2, v3);
            } else {
                store_hl2(ga.Yh, ga.Yl, idx, v0, v1);
                store_hl2(ga.Yh, ga.Yl, idx + 8 * (size_t)D, v2, v3);
            }
        }
    }
}

// ---------------------------------------------------------------------------
extern "C" void kernel_launch(void* const* d_in, const int* in_sizes, int n_in,
                              void* d_out, int out_size)
{
    const float* q_loc   = (const float*)d_in[0];
    const float* k_loc   = (const float*)d_in[2];
    const float* v_loc   = (const float*)d_in[4];
    const float* v_scale = (const float*)d_in[5];
    const float* Wq = (const float*)d_in[6];
    const float* bq = (const float*)d_in[7];
    const float* Wk = (const float*)d_in[8];
    const float* bk = (const float*)d_in[9];
    const float* Wv = (const float*)d_in[10];
    const float* bv = (const float*)d_in[11];
    const float* Wo = (const float*)d_in[12];
    const float* bo = (const float*)d_in[13];
    const float* tau = (const float*)d_in[14];

    float* out_loc   = (float*)d_out;
    float* out_scale = (float*)d_out + PROJ;

    float *lg, *cs;
    cudaGetSymbolAddress((void**)&lg, g_logits);
    cudaGetSymbolAddress((void**)&cs, g_colsum);
    bf16 *amuh, *amul, *avarw;
    cudaGetSymbolAddress((void**)&amuh, g_amuh); cudaGetSymbolAddress((void**)&amul, g_amul);
    cudaGetSymbolAddress((void**)&avarw, g_avarw);
    bf16 *qh,*ql,*kh,*kl,*vh,*vl,*vsh;
    cudaGetSymbolAddress((void**)&qh, g_qh);   cudaGetSymbolAddress((void**)&ql, g_ql);
    cudaGetSymbolAddress((void**)&kh, g_kh);   cudaGetSymbolAddress((void**)&kl, g_kl);
    cudaGetSymbolAddress((void**)&vh, g_vh);   cudaGetSymbolAddress((void**)&vl, g_vl);
    cudaGetSymbolAddress((void**)&vsh, g_vsh);
    bf16 *qmh,*qml,*kmh,*kml,*vmh,*vml,*vvh,*ymh,*yml,*pph;
    cudaGetSymbolAddress((void**)&qmh, g_qmh); cudaGetSymbolAddress((void**)&qml, g_qml);
    cudaGetSymbolAddress((void**)&kmh, g_kmh); cudaGetSymbolAddress((void**)&kml, g_kml);
    cudaGetSymbolAddress((void**)&vmh, g_vmh); cudaGetSymbolAddress((void**)&vml, g_vml);
    cudaGetSymbolAddress((void**)&vvh, g_vvh);
    cudaGetSymbolAddress((void**)&ymh, g_ymh); cudaGetSymbolAddress((void**)&yml, g_yml);
    cudaGetSymbolAddress((void**)&pph, g_pph);
    bf16 *wqh,*wql,*wkh,*wkl,*wvh,*wvl,*wvsh,*woh,*wol,*wosh;
    cudaGetSymbolAddress((void**)&wqh, g_wqh);   cudaGetSymbolAddress((void**)&wql, g_wql);
    cudaGetSymbolAddress((void**)&wkh, g_wkh);   cudaGetSymbolAddress((void**)&wkl, g_wkl);
    cudaGetSymbolAddress((void**)&wvh, g_wvh);   cudaGetSymbolAddress((void**)&wvl, g_wvl);
    cudaGetSymbolAddress((void**)&wvsh, g_wvsh);
    cudaGetSymbolAddress((void**)&woh, g_woh);   cudaGetSymbolAddress((void**)&wol, g_wol);
    cudaGetSymbolAddress((void**)&wosh, g_wosh);

    cudaFuncSetAttribute(gemm_mma_b, cudaFuncAttributeMaxDynamicSharedMemorySize, GSMEM);
    cudaFuncSetAttribute(qk_hmma,    cudaFuncAttributeMaxDynamicSharedMemorySize, QK_SMEM);
    cudaFuncSetAttribute(av_hmma_b,  cudaFuncAttributeMaxDynamicSharedMemorySize, AV_SMEM);

    // hi/lo conversion
    CvtParams P;
    const int PN = (int)PROJ, WN = (int)WSZ;
    P.src[0] = q_loc;   P.hi[0] = qh;   P.lo[0] = ql;      P.n[0] = PN; P.sq[0] = 0;
    P.src[1] = k_loc;   P.hi[1] = kh;   P.lo[1] = kl;      P.n[1] = PN; P.sq[1] = 0;
    P.src[2] = v_loc;   P.hi[2] = vh;   P.lo[2] = vl;      P.n[2] = PN; P.sq[2] = 0;
    P.src[3] = v_scale; P.hi[3] = vsh;  P.lo[3] = nullptr; P.n[3] = PN; P.sq[3] = 1;
    P.src[4] = Wq;      P.hi[4] = wqh;  P.lo[4] = wql;     P.n[4] = WN; P.sq[4] = 0;
    P.src[5] = Wk;      P.hi[5] = wkh;  P.lo[5] = wkl;     P.n[5] = WN; P.sq[5] = 0;
    P.src[6] = Wv;      P.hi[6] = wvh;  P.lo[6] = wvl;     P.n[6] = WN; P.sq[6] = 0;
    P.src[7] = Wv;      P.hi[7] = wvsh; P.lo[7] = nullptr; P.n[7] = WN; P.sq[7] = 1;
    P.src[8] = Wo;      P.hi[8] = woh;  P.lo[8] = wol;     P.n[8] = WN; P.sq[8] = 0;
    P.src[9] = Wo;      P.hi[9] = wosh; P.lo[9] = nullptr; P.n[9] = WN; P.sq[9] = 1;
    P.cs = cs;
    convert_all<<<dim3(PN / 1024, 10), 256>>>(P);

    // batched projections
    GemmBatch bp;
    bp.a[0] = { qh,  ql,      wqh,  wql,    bq,      nullptr, qmh, qml,     3, 3 };
    bp.a[1] = { kh,  kl,      wkh,  wkl,    bk,      nullptr, kmh, kml,     3, 3 };
    bp.a[2] = { vh,  vl,      wvh,  wvl,    bv,      nullptr, vmh, vml,     3, 3 };
    bp.a[3] = { vsh, nullptr, wvsh, nullptr,nullptr, nullptr, vvh, nullptr, 5, 1 };
    gemm_mma_b<<<dim3(GN / 128, BS / 128, 4), 512, GSMEM>>>(bp);

    // colsum over t of vvar
    colsum_kernel<<<dim3(B * D / 256, S / 64), 256>>>(cs, vvh);

    // attention
    qk_hmma<<<dim3(S / 128, S / 128, B * H), 256, QK_SMEM>>>(lg, qmh, qml, kmh, kml, tau);
    softmax_kernel<<<B * H * S, 256>>>(amuh, amul, avarw, lg, tau);

    // batched AV: z=0 mean (3-pass), z=1 variance (1-pass + colsum)
    AvBatch av;
    av.a[0] = { ymh, yml,     amuh,  amul,    vmh, vml,     nullptr, 0 };
    av.a[1] = { pph, nullptr, avarw, nullptr, vvh, nullptr, cs,      1 };
    av_hmma_b<<<dim3(S / 128, B * H, 2), 256, AV_SMEM>>>(av);

    // batched output projections
    GemmBatch bo2;
    bo2.a[0] = { ymh, yml,     woh,  wol,    bo,      out_loc,   nullptr, nullptr, 0, 3 };
    bo2.a[1] = { pph, nullptr, wosh, nullptr,nullptr, out_scale, nullptr, nullptr, 2, 1 };
    bo2.a[2] = bo2.a[0];
    bo2.a[3] = bo2.a[0];
    gemm_mma_b<<<dim3(GN / 128, BS / 128, 2), 512, GSMEM>>>(bo2);
}